// round 15
// baseline (speedup 1.0000x reference)
#include <cuda_runtime.h>
#include <cuda_bf16.h>
#include <math.h>
#include <stdint.h>

#define NHEAD 12
#define HDIM  64
#define DM    768
#define SEQ   2048
#define BATCH 4
#define MTOT  (BATCH * SEQ)
#define HALFD 384

// ---------------------------------------------------------------------------
// Scratch (allocation-free rule: __device__ globals)
// ---------------------------------------------------------------------------
__device__ __nv_bfloat16 g_Qh[(size_t)MTOT * DM];
__device__ __nv_bfloat16 g_Ql[(size_t)MTOT * DM];
__device__ __nv_bfloat16 g_Kh[(size_t)MTOT * DM];
__device__ __nv_bfloat16 g_Kl[(size_t)MTOT * DM];
__device__ __nv_bfloat16 g_Vh[(size_t)MTOT * DM];
__device__ __nv_bfloat16 g_Vl[(size_t)MTOT * DM];
__device__ __nv_bfloat16 g_Eh[(size_t)MTOT * DM];
__device__ __nv_bfloat16 g_El[(size_t)MTOT * DM];
__device__ __nv_bfloat16 g_Xh[(size_t)MTOT * DM];
__device__ __nv_bfloat16 g_Xl[(size_t)MTOT * DM];
__device__ __nv_bfloat16 g_WTh[(size_t)4 * DM * DM];
__device__ __nv_bfloat16 g_WTl[(size_t)4 * DM * DM];
__device__ float g_cosT[(size_t)SEQ * HALFD];
__device__ float g_sinT[(size_t)SEQ * HALFD];

// ---------------------------------------------------------------------------
// Arch-neutral PTX helpers (mma.sync / ldmatrix / cp.async)
// ---------------------------------------------------------------------------
__device__ __forceinline__ uint32_t smem_u32(const void* p) {
    uint32_t a;
    asm("{ .reg .u64 t; cvta.to.shared.u64 t, %1; cvt.u32.u64 %0, t; }"
        : "=r"(a) : "l"(p));
    return a;
}
__device__ __forceinline__ void ldsm4(uint32_t* r, uint32_t addr) {
    asm volatile("ldmatrix.sync.aligned.m8n8.x4.shared.b16 {%0,%1,%2,%3}, [%4];"
                 : "=r"(r[0]), "=r"(r[1]), "=r"(r[2]), "=r"(r[3]) : "r"(addr));
}
__device__ __forceinline__ void ldsm4t(uint32_t* r, uint32_t addr) {
    asm volatile("ldmatrix.sync.aligned.m8n8.x4.trans.shared.b16 {%0,%1,%2,%3}, [%4];"
                 : "=r"(r[0]), "=r"(r[1]), "=r"(r[2]), "=r"(r[3]) : "r"(addr));
}
__device__ __forceinline__ void mma_bf16(float* c, const uint32_t* a,
                                         uint32_t b0, uint32_t b1) {
    asm volatile(
        "mma.sync.aligned.m16n8k16.row.col.f32.bf16.bf16.f32 "
        "{%0,%1,%2,%3}, {%4,%5,%6,%7}, {%8,%9}, {%0,%1,%2,%3};"
        : "+f"(c[0]), "+f"(c[1]), "+f"(c[2]), "+f"(c[3])
        : "r"(a[0]), "r"(a[1]), "r"(a[2]), "r"(a[3]), "r"(b0), "r"(b1));
}
__device__ __forceinline__ void cp16(uint32_t sdst, const void* gsrc) {
    asm volatile("cp.async.cg.shared.global [%0], [%1], 16;"
                 :: "r"(sdst), "l"(gsrc) : "memory");
}
#define CP_COMMIT() asm volatile("cp.async.commit_group;" ::: "memory")
#define CP_WAIT(n)  asm volatile("cp.async.wait_group %0;" :: "n"(n) : "memory")

__device__ __forceinline__ uint32_t packbf(float a, float b) {
    __nv_bfloat162 t = __floats2bfloat162_rn(a, b);
    return *reinterpret_cast<uint32_t*>(&t);
}
__device__ __forceinline__ uint32_t packh(__nv_bfloat16 a, __nv_bfloat16 b) {
    __nv_bfloat162 t = __halves2bfloat162(a, b);
    return *reinterpret_cast<uint32_t*>(&t);
}

// ---------------------------------------------------------------------------
// Prep kernels
// ---------------------------------------------------------------------------
__global__ void rope_table_kernel(float* __restrict__ cosT, float* __restrict__ sinT) {
    int idx = blockIdx.x * 256 + threadIdx.x;
    if (idx >= SEQ * HALFD) return;
    int s = idx / HALFD, i = idx - s * HALFD;
    float invf = expf(-((float)i) * (2.0f / (float)DM) * 9.210340371976184f);
    float c, sn;
    sincosf((float)s * invf, &sn, &c);
    cosT[idx] = c;
    sinT[idx] = sn;
}

__global__ void split_kernel(const float* __restrict__ in,
                             __nv_bfloat16* __restrict__ hi,
                             __nv_bfloat16* __restrict__ lo, int n2) {
    int i = blockIdx.x * 256 + threadIdx.x;
    if (i >= n2) return;
    float2 v = ((const float2*)in)[i];
    __nv_bfloat16 hx = __float2bfloat16(v.x), hy = __float2bfloat16(v.y);
    __nv_bfloat16 lx = __float2bfloat16(v.x - __bfloat162float(hx));
    __nv_bfloat16 ly = __float2bfloat16(v.y - __bfloat162float(hy));
    ((__nv_bfloat162*)hi)[i] = __halves2bfloat162(hx, hy);
    ((__nv_bfloat162*)lo)[i] = __halves2bfloat162(lx, ly);
}

// Fused 4-way W transpose+split; blockIdx.z selects the matrix.
__global__ void wsplit4_kernel(const float* __restrict__ Wq, const float* __restrict__ Wk,
                               const float* __restrict__ Wv, const float* __restrict__ Wo,
                               __nv_bfloat16* __restrict__ TThAll,
                               __nv_bfloat16* __restrict__ TTlAll) {
    __shared__ float t[32][33];
    const int z = blockIdx.z;
    const float* W = (z == 0) ? Wq : (z == 1) ? Wk : (z == 2) ? Wv : Wo;
    const size_t WSZ = (size_t)DM * DM;
    __nv_bfloat16* Th = TThAll + (size_t)z * WSZ;
    __nv_bfloat16* Tl = TTlAll + (size_t)z * WSZ;
    int bx = blockIdx.x << 5, by = blockIdx.y << 5;
    int x = threadIdx.x, y = threadIdx.y;
#pragma unroll
    for (int i = 0; i < 32; i += 8)
        t[y + i][x] = W[(size_t)(by + y + i) * DM + bx + x];
    __syncthreads();
#pragma unroll
    for (int i = 0; i < 32; i += 8) {
        float v = t[x][y + i];
        __nv_bfloat16 h = __float2bfloat16(v);
        size_t o = (size_t)(bx + y + i) * DM + by + x;
        Th[o] = h;
        Tl[o] = __float2bfloat16(v - __bfloat162float(h));
    }
}

// ---------------------------------------------------------------------------
// HMMA bf16-split GEMM cores — CTA tile 128x64, 256 threads, 8 warps (4m x 2n),
// warp-tile 32x32. 96KB smem -> 2 CTAs/SM (barrier-decoupled).
// ---------------------------------------------------------------------------
#define ATILE_B  16384            // 128 rows x 128B
#define BTILE_B  8192             // 64 rows x 128B
#define SO_AH    0
#define SO_AL    16384
#define SO_BH    32768
#define SO_BL    40960
#define GBUF     49152
#define GEMM_SMEM (2 * GBUF)      // 98304
#define NCHUNK   (DM / 64)
#define GTHREADS 256

// 256-thread fill: A 2 thr/row x 4 cp16; B 4 thr/row x 2 cp16 (per hi/lo tile)
#define GEMM_FILL(buf, c)                                                     \
    do {                                                                      \
        const uint32_t bb = sb + (buf) * GBUF;                                \
        const int kbB = (c) * 128;                                            \
        _Pragma("unroll")                                                     \
        for (int q = 0; q < 4; ++q) {                                         \
            uint32_t o = faoff + q * 16;                                      \
            uint32_t sw = o ^ ((o >> 3) & 0x70);                              \
            cp16(bb + SO_AH + sw, pAh + kbB + q * 16);                        \
            cp16(bb + SO_AL + sw, pAl + kbB + q * 16);                        \
        }                                                                     \
        _Pragma("unroll")                                                     \
        for (int q = 0; q < 2; ++q) {                                         \
            uint32_t o = fboff + q * 16;                                      \
            uint32_t sw = o ^ ((o >> 3) & 0x70);                              \
            cp16(bb + SO_BH + sw, pBh + kbB + q * 16);                        \
            cp16(bb + SO_BL + sw, pBl + kbB + q * 16);                        \
        }                                                                     \
    } while (0)

#define GEMM_MAINLOOP()                                                       \
    GEMM_FILL(0, 0);                                                          \
    CP_COMMIT();                                                              \
    for (int c = 0; c < NCHUNK; ++c) {                                        \
        if (c + 1 < NCHUNK) {                                                 \
            GEMM_FILL((c + 1) & 1, c + 1);                                    \
            CP_COMMIT();                                                      \
            CP_WAIT(1);                                                       \
        } else {                                                              \
            CP_WAIT(0);                                                       \
        }                                                                     \
        __syncthreads();                                                      \
        const uint32_t base = sb + (c & 1) * GBUF;                            \
        _Pragma("unroll")                                                     \
        for (int kk = 0; kk < 4; ++kk) {                                      \
            uint32_t ahf[2][4], alf[2][4], bhf[2][4], blf[2][4];              \
            _Pragma("unroll")                                                 \
            for (int mi = 0; mi < 2; ++mi) {                                  \
                uint32_t o = (uint32_t)(wm * 32 + mi * 16 + lrow) * 128 + kk * 32 + lhi; \
                uint32_t sw = o ^ ((o >> 3) & 0x70);                          \
                ldsm4(ahf[mi], base + SO_AH + sw);                            \
                ldsm4(alf[mi], base + SO_AL + sw);                            \
            }                                                                 \
            _Pragma("unroll")                                                 \
            for (int nt = 0; nt < 2; ++nt) {                                  \
                uint32_t o = (uint32_t)(wn * 32 + nt * 16 + lrow) * 128 + kk * 32 + lhi; \
                uint32_t sw = o ^ ((o >> 3) & 0x70);                          \
                ldsm4(bhf[nt], base + SO_BH + sw);                            \
                ldsm4(blf[nt], base + SO_BL + sw);                            \
            }                                                                 \
            _Pragma("unroll")                                                 \
            for (int mi = 0; mi < 2; ++mi)                                    \
                _Pragma("unroll")                                             \
                for (int nj = 0; nj < 4; ++nj) {                              \
                    const int nt = nj >> 1, hb = nj & 1;                      \
                    mma_bf16(acc[mi][nj], ahf[mi], bhf[nt][hb], bhf[nt][hb + 2]); \
                    mma_bf16(acc[mi][nj], ahf[mi], blf[nt][hb], blf[nt][hb + 2]); \
                    mma_bf16(acc[mi][nj], alf[mi], bhf[nt][hb], bhf[nt][hb + 2]); \
                }                                                             \
        }                                                                     \
        __syncthreads();                                                      \
    }

// Fused QKV projection: grid (36, 64) = (proj*12 + coltile, rowtile)
__global__ __launch_bounds__(GTHREADS, 2)
void gemm_qkv(const __nv_bfloat16* __restrict__ Xh, const __nv_bfloat16* __restrict__ Xl,
              const __nv_bfloat16* __restrict__ WTh, const __nv_bfloat16* __restrict__ WTl,
              const float* __restrict__ bq, const float* __restrict__ bk,
              const float* __restrict__ bv,
              const float* __restrict__ cosT, const float* __restrict__ sinT,
              __nv_bfloat16* __restrict__ Qh, __nv_bfloat16* __restrict__ Ql,
              __nv_bfloat16* __restrict__ Kh, __nv_bfloat16* __restrict__ Kl,
              __nv_bfloat16* __restrict__ Vh, __nv_bfloat16* __restrict__ Vl)
{
    extern __shared__ char smc[];
    const uint32_t sb = smem_u32(smc);
    const int tid = threadIdx.x;
    const int wid = tid >> 5, lane = tid & 31;
    const int wm = wid & 3, wn = wid >> 2;   // 4 (m) x 2 (n)
    const int pj = blockIdx.x / 12;
    const int col0 = (blockIdx.x - pj * 12) << 6;
    const int row0 = blockIdx.y << 7;
    const int lrow = lane & 15, lhi = (lane >> 4) << 4;

    const size_t WSZ = (size_t)DM * DM;
    const __nv_bfloat16* Bh = WTh + (size_t)pj * WSZ;
    const __nv_bfloat16* Bl = WTl + (size_t)pj * WSZ;
    const float* bias = (pj == 0) ? bq : (pj == 1) ? bk : bv;
    __nv_bfloat16* outH = (pj == 0) ? Qh : (pj == 1) ? Kh : Vh;
    __nv_bfloat16* outL = (pj == 0) ? Ql : (pj == 1) ? Kl : Vl;
    const int doRope = (pj < 2);
    const float scale = (pj == 0) ? 0.125f : 1.0f;

    float acc[2][4][4];
#pragma unroll
    for (int i = 0; i < 2; ++i)
#pragma unroll
        for (int j = 0; j < 4; ++j)
#pragma unroll
            for (int q = 0; q < 4; ++q) acc[i][j][q] = 0.f;

    const int farow = tid >> 1, facb = (tid & 1) << 6;
    const int fbrow = tid >> 2, fbcb = (tid & 3) << 5;
    const uint32_t faoff = farow * 128 + facb;
    const uint32_t fboff = fbrow * 128 + fbcb;
    const char* pAh = (const char*)(Xh + (size_t)(row0 + farow) * DM) + facb;
    const char* pAl = (const char*)(Xl + (size_t)(row0 + farow) * DM) + facb;
    const char* pBh = (const char*)(Bh + (size_t)(col0 + fbrow) * DM) + fbcb;
    const char* pBl = (const char*)(Bl + (size_t)(col0 + fbrow) * DM) + fbcb;

    GEMM_MAINLOOP();

    const int qr = lane >> 2, qc = (lane & 3) << 1;
#pragma unroll
    for (int mi = 0; mi < 2; ++mi)
#pragma unroll
        for (int nj = 0; nj < 4; ++nj) {
            const int col = col0 + wn * 32 + nj * 8 + qc;
            const float b0 = __ldg(bias + col), b1 = __ldg(bias + col + 1);
#pragma unroll
            for (int hf = 0; hf < 2; ++hf) {
                const int grow = row0 + wm * 32 + mi * 16 + qr + hf * 8;
                float v0 = acc[mi][nj][hf * 2 + 0] + b0;
                float v1 = acc[mi][nj][hf * 2 + 1] + b1;
                if (doRope) {
                    const int srow = grow & (SEQ - 1);
                    const size_t ti = (size_t)srow * HALFD + (col >> 1);
                    const float cs = cosT[ti], sn = sinT[ti];
                    const float r0 = v0 * cs - v1 * sn;
                    const float r1 = v0 * sn + v1 * cs;
                    v0 = r0; v1 = r1;
                }
                v0 *= scale; v1 *= scale;
                __nv_bfloat16 h0 = __float2bfloat16(v0), h1 = __float2bfloat16(v1);
                *reinterpret_cast<uint32_t*>(outH + (size_t)grow * DM + col) = packh(h0, h1);
                *reinterpret_cast<uint32_t*>(outL + (size_t)grow * DM + col) =
                    packbf(v0 - __bfloat162float(h0), v1 - __bfloat162float(h1));
            }
        }
}

// Output projection (fp32 out): grid (12, 64)
__global__ __launch_bounds__(GTHREADS, 2)
void gemm_mma(const __nv_bfloat16* __restrict__ Ah, const __nv_bfloat16* __restrict__ Al,
              const __nv_bfloat16* __restrict__ Bhp, const __nv_bfloat16* __restrict__ Blp,
              const float* __restrict__ bias, float* __restrict__ outF)
{
    extern __shared__ char smc[];
    const uint32_t sb = smem_u32(smc);
    const int tid = threadIdx.x;
    const int wid = tid >> 5, lane = tid & 31;
    const int wm = wid & 3, wn = wid >> 2;
    const int col0 = blockIdx.x << 6, row0 = blockIdx.y << 7;
    const int lrow = lane & 15, lhi = (lane >> 4) << 4;

    float acc[2][4][4];
#pragma unroll
    for (int i = 0; i < 2; ++i)
#pragma unroll
        for (int j = 0; j < 4; ++j)
#pragma unroll
            for (int q = 0; q < 4; ++q) acc[i][j][q] = 0.f;

    const int farow = tid >> 1, facb = (tid & 1) << 6;
    const int fbrow = tid >> 2, fbcb = (tid & 3) << 5;
    const uint32_t faoff = farow * 128 + facb;
    const uint32_t fboff = fbrow * 128 + fbcb;
    const char* pAh = (const char*)(Ah + (size_t)(row0 + farow) * DM) + facb;
    const char* pAl = (const char*)(Al + (size_t)(row0 + farow) * DM) + facb;
    const char* pBh = (const char*)(Bhp + (size_t)(col0 + fbrow) * DM) + fbcb;
    const char* pBl = (const char*)(Blp + (size_t)(col0 + fbrow) * DM) + fbcb;

    GEMM_MAINLOOP();

    const int qr = lane >> 2, qc = (lane & 3) << 1;
#pragma unroll
    for (int mi = 0; mi < 2; ++mi)
#pragma unroll
        for (int nj = 0; nj < 4; ++nj) {
            const int col = col0 + wn * 32 + nj * 8 + qc;
            const float b0 = __ldg(bias + col), b1 = __ldg(bias + col + 1);
#pragma unroll
            for (int hf = 0; hf < 2; ++hf) {
                const int grow = row0 + wm * 32 + mi * 16 + qr + hf * 8;
                *(float2*)(outF + (size_t)grow * DM + col) =
                    make_float2(acc[mi][nj][hf * 2 + 0] + b0,
                                acc[mi][nj][hf * 2 + 1] + b1);
            }
        }
}

// ---------------------------------------------------------------------------
// Flash attention via HMMA (unchanged — passing, 2 CTA/SM)
// ---------------------------------------------------------------------------
#define AQ_H 0
#define AQ_L 16384
#define ABUF0 32768
#define KVBUF 32768
#define BT_KH 0
#define BT_KL 8192
#define BT_VH 16384
#define BT_VL 24576
#define ATTN_SMEM (ABUF0 + 2 * KVBUF)  // 98304

__global__ __launch_bounds__(256, 2)
void attn_mma(const __nv_bfloat16* __restrict__ Qh, const __nv_bfloat16* __restrict__ Ql,
              const __nv_bfloat16* __restrict__ Kh, const __nv_bfloat16* __restrict__ Kl,
              const __nv_bfloat16* __restrict__ Vh, const __nv_bfloat16* __restrict__ Vl,
              __nv_bfloat16* __restrict__ Eh, __nv_bfloat16* __restrict__ El)
{
    extern __shared__ char smc[];
    const uint32_t sb = smem_u32(smc);
    const int tid = threadIdx.x, wq = tid >> 5, lane = tid & 31;
    const int bh = blockIdx.y, b = bh / NHEAD, h = bh - (bh / NHEAD) * NHEAD;
    const int qt = gridDim.x - 1 - blockIdx.x;  // heavy tiles first
    const int q0 = qt << 7;
    const int nch = 2 * qt + 2;
    const size_t base = (size_t)b * SEQ * DM + (size_t)h * HDIM;

    const int frow = tid >> 1, fcb = (tid & 1) << 6;
    uint32_t fsw[4];
#pragma unroll
    for (int q = 0; q < 4; ++q) {
        uint32_t o = (uint32_t)frow * 128 + fcb + q * 16;
        fsw[q] = o ^ ((o >> 3) & 0x70);
    }
    const int frow2 = tid >> 2, fcb2 = (tid & 3) << 5;
    uint32_t fsw2[2];
#pragma unroll
    for (int q = 0; q < 2; ++q) {
        uint32_t o = (uint32_t)frow2 * 128 + fcb2 + q * 16;
        fsw2[q] = o ^ ((o >> 3) & 0x70);
    }

    {
        const char* pQh = (const char*)(Qh + base + (size_t)(q0 + frow) * DM) + fcb;
        const char* pQl = (const char*)(Ql + base + (size_t)(q0 + frow) * DM) + fcb;
#pragma unroll
        for (int q = 0; q < 4; ++q) {
            cp16(sb + AQ_H + fsw[q], pQh + q * 16);
            cp16(sb + AQ_L + fsw[q], pQl + q * 16);
        }
    }
#define AFILL(bufbase, kb)                                                    \
    do {                                                                      \
        const char* pKh = (const char*)(Kh + base + (size_t)((kb) + frow2) * DM) + fcb2; \
        const char* pKl = (const char*)(Kl + base + (size_t)((kb) + frow2) * DM) + fcb2; \
        const char* pVh = (const char*)(Vh + base + (size_t)((kb) + frow2) * DM) + fcb2; \
        const char* pVl = (const char*)(Vl + base + (size_t)((kb) + frow2) * DM) + fcb2; \
        _Pragma("unroll")                                                     \
        for (int q = 0; q < 2; ++q) {                                         \
            cp16((bufbase) + BT_KH + fsw2[q], pKh + q * 16);                  \
            cp16((bufbase) + BT_KL + fsw2[q], pKl + q * 16);                  \
            cp16((bufbase) + BT_VH + fsw2[q], pVh + q * 16);                  \
            cp16((bufbase) + BT_VL + fsw2[q], pVl + q * 16);                  \
        }                                                                     \
    } while (0)

    AFILL(sb + ABUF0, 0);
    CP_COMMIT();
    CP_WAIT(0);
    __syncthreads();

    float m0 = -1e30f, m1 = -1e30f, l0 = 0.f, l1 = 0.f;
    float o_[8][4];
#pragma unroll
    for (int i = 0; i < 8; ++i)
#pragma unroll
        for (int j = 0; j < 4; ++j) o_[i][j] = 0.f;

    const int lrow = lane & 15, lhi = (lane >> 4) << 4;
    const int vrow = ((lane >> 3) & 1) * 8 + (lane & 7);
    const int vcol = (lane >> 4) << 4;

    for (int c = 0; c < nch; ++c) {
        const int kb = c << 6;
        if (c + 1 < nch) {
            AFILL(sb + ABUF0 + ((c + 1) & 1) * KVBUF, (c + 1) << 6);
            CP_COMMIT();
        }
        if (c > 0) {
            if (c + 1 < nch) { CP_WAIT(1); } else { CP_WAIT(0); }
        }
        __syncthreads();
        const uint32_t tb = sb + ABUF0 + (c & 1) * KVBUF;

        float s[8][4];
#pragma unroll
        for (int i = 0; i < 8; ++i)
#pragma unroll
            for (int j = 0; j < 4; ++j) s[i][j] = 0.f;

#pragma unroll
        for (int kk = 0; kk < 4; ++kk) {
            uint32_t aqh[4], aql[4];
            {
                uint32_t o = (uint32_t)(wq * 16 + lrow) * 128 + kk * 32 + lhi;
                uint32_t sw = o ^ ((o >> 3) & 0x70);
                ldsm4(aqh, sb + AQ_H + sw);
                ldsm4(aql, sb + AQ_L + sw);
            }
#pragma unroll
            for (int g = 0; g < 4; ++g) {
                uint32_t o = (uint32_t)(g * 16 + lrow) * 128 + kk * 32 + lhi;
                uint32_t sw = o ^ ((o >> 3) & 0x70);
                uint32_t kh[4], kl[4];
                ldsm4(kh, tb + BT_KH + sw);
                ldsm4(kl, tb + BT_KL + sw);
                mma_bf16(s[2 * g],     aqh, kh[0], kh[2]);
                mma_bf16(s[2 * g],     aqh, kl[0], kl[2]);
                mma_bf16(s[2 * g],     aql, kh[0], kh[2]);
                mma_bf16(s[2 * g + 1], aqh, kh[1], kh[3]);
                mma_bf16(s[2 * g + 1], aqh, kl[1], kl[3]);
                mma_bf16(s[2 * g + 1], aql, kh[1], kh[3]);
            }
        }

        const int dq = q0 - kb;
        if (dq < 128) {
            const int qr0 = wq * 16 + (lane >> 2);
            const int kbn = (lane & 3) << 1;
            const int th0 = qr0 + dq, th1 = qr0 + 8 + dq;
#pragma unroll
            for (int jb = 0; jb < 8; ++jb) {
                const int k0 = jb * 8 + kbn;
                if (k0 > th0)     s[jb][0] = -1e30f;
                if (k0 + 1 > th0) s[jb][1] = -1e30f;
                if (k0 > th1)     s[jb][2] = -1e30f;
                if (k0 + 1 > th1) s[jb][3] = -1e30f;
            }
        }

        float mx0 = -1e30f, mx1 = -1e30f;
#pragma unroll
        for (int jb = 0; jb < 8; ++jb) {
            mx0 = fmaxf(mx0, fmaxf(s[jb][0], s[jb][1]));
            mx1 = fmaxf(mx1, fmaxf(s[jb][2], s[jb][3]));
        }
        mx0 = fmaxf(mx0, __shfl_xor_sync(0xffffffffu, mx0, 1));
        mx0 = fmaxf(mx0, __shfl_xor_sync(0xffffffffu, mx0, 2));
        mx1 = fmaxf(mx1, __shfl_xor_sync(0xffffffffu, mx1, 1));
        mx1 = fmaxf(mx1, __shfl_xor_sync(0xffffffffu, mx1, 2));
        const float mn0 = fmaxf(m0, mx0), mn1 = fmaxf(m1, mx1);
        const float c0 = __expf(m0 - mn0), c1 = __expf(m1 - mn1);
        float sum0 = 0.f, sum1 = 0.f;
#pragma unroll
        for (int jb = 0; jb < 8; ++jb) {
            s[jb][0] = __expf(s[jb][0] - mn0);
            s[jb][1] = __expf(s[jb][1] - mn0);
            s[jb][2] = __expf(s[jb][2] - mn1);
            s[jb][3] = __expf(s[jb][3] - mn1);
            sum0 += s[jb][0] + s[jb][1];
            sum1 += s[jb][2] + s[jb][3];
        }
        sum0 += __shfl_xor_sync(0xffffffffu, sum0, 1);
        sum0 += __shfl_xor_sync(0xffffffffu, sum0, 2);
        sum1 += __shfl_xor_sync(0xffffffffu, sum1, 1);
        sum1 += __shfl_xor_sync(0xffffffffu, sum1, 2);
        l0 = l0 * c0 + sum0;
        l1 = l1 * c1 + sum1;
        m0 = mn0; m1 = mn1;
#pragma unroll
        for (int db = 0; db < 8; ++db) {
            o_[db][0] *= c0; o_[db][1] *= c0;
            o_[db][2] *= c1; o_[db][3] *= c1;
        }

#pragma unroll
        for (int t = 0; t < 4; ++t) {
            uint32_t pah[4], pal[4];
            {
                const float f0 = s[2 * t][0], f1 = s[2 * t][1];
                const float f2 = s[2 * t][2], f3 = s[2 * t][3];
                __nv_bfloat16 h0 = __float2bfloat16(f0), h1 = __float2bfloat16(f1);
                __nv_bfloat16 h2 = __float2bfloat16(f2), h3 = __float2bfloat16(f3);
                pah[0] = packh(h0, h1);
                pah[1] = packh(h2, h3);
                pal[0] = packbf(f0 - __bfloat162float(h0), f1 - __bfloat162float(h1));
                pal[1] = packbf(f2 - __bfloat162float(h2), f3 - __bfloat162float(h3));
            }
            {
                const float f0 = s[2 * t + 1][0], f1 = s[2 * t + 1][1];
                const float f2 = s[2 * t + 1][2], f3 = s[2 * t + 1][3];
                __nv_bfloat16 h0 = __float2bfloat16(f0), h1 = __float2bfloat16(f1);
                __nv_bfloat16 h2 = __float2bfloat16(f2), h3 = __float2bfloat16(f3);
                pah[2] = packh(h0, h1);
                pah[3] = packh(h2, h3);
                pal[2] = packbf(f0 - __bfloat162float(h0), f1 - __bfloat162float(h1));
                pal[3] = packbf(f2 - __bfloat162float(h2), f3 - __bfloat162float(h3));
            }
#pragma unroll
            for (int g = 0; g < 4; ++g) {
                uint32_t o = (uint32_t)(t * 16 + vrow) * 128 + g * 32 + vcol;
                uint32_t sw = o ^ ((o >> 3) & 0x70);
                uint32_t vh[4], vl[4];
                ldsm4t(vh, tb + BT_VH + sw);
                ldsm4t(vl, tb + BT_VL + sw);
                mma_bf16(o_[2 * g],     pah, vh[0], vh[1]);
                mma_bf16(o_[2 * g],     pal, vh[0], vh[1]);
                mma_bf16(o_[2 * g],     pah, vl[0], vl[1]);
                mma_bf16(o_[2 * g + 1], pah, vh[2], vh[3]);
                mma_bf16(o_[2 * g + 1], pal, vh[2], vh[3]);
                mma_bf16(o_[2 * g + 1], pah, vl[2], vl[3]);
            }
        }
        __syncthreads();
    }

    const float inv0 = 1.0f / l0, inv1 = 1.0f / l1;
    const int r0g = q0 + wq * 16 + (lane >> 2);
    const size_t ro0 = base + (size_t)r0g * DM;
    const size_t ro1 = ro0 + (size_t)8 * DM;
    const int cb = (lane & 3) << 1;
#pragma unroll
    for (int db = 0; db < 8; ++db) {
        const int col = db * 8 + cb;
        {
            const float f0 = o_[db][0] * inv0, f1 = o_[db][1] * inv0;
            __nv_bfloat16 h0 = __float2bfloat16(f0), h1 = __float2bfloat16(f1);
            *reinterpret_cast<uint32_t*>(Eh + ro0 + col) = packh(h0, h1);
            *reinterpret_cast<uint32_t*>(El + ro0 + col) =
                packbf(f0 - __bfloat162float(h0), f1 - __bfloat162float(h1));
        }
        {
            const float f2 = o_[db][2] * inv1, f3 = o_[db][3] * inv1;
            __nv_bfloat16 h2 = __float2bfloat16(f2), h3 = __float2bfloat16(f3);
            *reinterpret_cast<uint32_t*>(Eh + ro1 + col) = packh(h2, h3);
            *reinterpret_cast<uint32_t*>(El + ro1 + col) =
                packbf(f2 - __bfloat162float(h2), f3 - __bfloat162float(h3));
        }
    }
}

// ---------------------------------------------------------------------------
// Launch
// ---------------------------------------------------------------------------
extern "C" void kernel_launch(void* const* d_in, const int* in_sizes, int n_in,
                              void* d_out, int out_size)
{
    const float* X  = (const float*)d_in[0];
    const float* Wq = (const float*)d_in[1];
    const float* bq = (const float*)d_in[2];
    const float* Wk = (const float*)d_in[3];
    const float* bk = (const float*)d_in[4];
    const float* Wv = (const float*)d_in[5];
    const float* bv = (const float*)d_in[6];
    const float* Wo = (const float*)d_in[7];
    const float* bo = (const float*)d_in[8];
    float* out = (float*)d_out;

    float *cosT, *sinT;
    __nv_bfloat16 *Qh, *Ql, *Kh, *Kl, *Vh, *Vl, *Eh, *El, *Xh, *Xl, *WTh, *WTl;
    cudaGetSymbolAddress((void**)&cosT, g_cosT);
    cudaGetSymbolAddress((void**)&sinT, g_sinT);
    cudaGetSymbolAddress((void**)&Qh, g_Qh);
    cudaGetSymbolAddress((void**)&Ql, g_Ql);
    cudaGetSymbolAddress((void**)&Kh, g_Kh);
    cudaGetSymbolAddress((void**)&Kl, g_Kl);
    cudaGetSymbolAddress((void**)&Vh, g_Vh);
    cudaGetSymbolAddress((void**)&Vl, g_Vl);
    cudaGetSymbolAddress((void**)&Eh, g_Eh);
    cudaGetSymbolAddress((void**)&El, g_El);
    cudaGetSymbolAddress((void**)&Xh, g_Xh);
    cudaGetSymbolAddress((void**)&Xl, g_Xl);
    cudaGetSymbolAddress((void**)&WTh, g_WTh);
    cudaGetSymbolAddress((void**)&WTl, g_WTl);

    cudaFuncSetAttribute(gemm_qkv, cudaFuncAttributeMaxDynamicSharedMemorySize, GEMM_SMEM);
    cudaFuncSetAttribute(gemm_mma, cudaFuncAttributeMaxDynamicSharedMemorySize, GEMM_SMEM);
    cudaFuncSetAttribute(attn_mma, cudaFuncAttributeMaxDynamicSharedMemorySize, ATTN_SMEM);

    const size_t WSZ = (size_t)DM * DM;

    rope_table_kernel<<<(SEQ * HALFD + 255) / 256, 256>>>(cosT, sinT);

    wsplit4_kernel<<<dim3(DM / 32, DM / 32, 4), dim3(32, 8)>>>(
        Wq, Wk, Wv, Wo, WTh, WTl);

    const int NP = MTOT * DM / 2;
    split_kernel<<<(NP + 255) / 256, 256>>>(X, Xh, Xl, NP);

    gemm_qkv<<<dim3(36, MTOT / 128), GTHREADS, GEMM_SMEM>>>(
        Xh, Xl, WTh, WTl, bq, bk, bv, cosT, sinT, Qh, Ql, Kh, Kl, Vh, Vl);

    attn_mma<<<dim3(SEQ / 128, BATCH * NHEAD), 256, ATTN_SMEM>>>(Qh, Ql, Kh, Kl,
                                                                 Vh, Vl, Eh, El);

    gemm_mma<<<dim3(DM / 64, MTOT / 128), GTHREADS, GEMM_SMEM>>>(
        Eh, El, WTh + 3 * WSZ, WTl + 3 * WSZ, bo, out);
}

// round 16
// speedup vs baseline: 1.0329x; 1.0329x over previous
#include <cuda_runtime.h>
#include <cuda_bf16.h>
#include <math.h>
#include <stdint.h>

#define NHEAD 12
#define HDIM  64
#define DM    768
#define SEQ   2048
#define BATCH 4
#define MTOT  (BATCH * SEQ)
#define HALFD 384

// ---------------------------------------------------------------------------
// Scratch (allocation-free rule: __device__ globals)
// ---------------------------------------------------------------------------
__device__ __nv_bfloat16 g_Qh[(size_t)MTOT * DM];
__device__ __nv_bfloat16 g_Ql[(size_t)MTOT * DM];
__device__ __nv_bfloat16 g_Kh[(size_t)MTOT * DM];
__device__ __nv_bfloat16 g_Kl[(size_t)MTOT * DM];
__device__ __nv_bfloat16 g_Vh[(size_t)MTOT * DM];
__device__ __nv_bfloat16 g_Vl[(size_t)MTOT * DM];
__device__ __nv_bfloat16 g_Eh[(size_t)MTOT * DM];
__device__ __nv_bfloat16 g_El[(size_t)MTOT * DM];
__device__ __nv_bfloat16 g_Xh[(size_t)MTOT * DM];
__device__ __nv_bfloat16 g_Xl[(size_t)MTOT * DM];
__device__ __nv_bfloat16 g_WTh[(size_t)4 * DM * DM];
__device__ __nv_bfloat16 g_WTl[(size_t)4 * DM * DM];
__device__ float g_cosT[(size_t)SEQ * HALFD];
__device__ float g_sinT[(size_t)SEQ * HALFD];

// ---------------------------------------------------------------------------
// Arch-neutral PTX helpers (mma.sync / ldmatrix / cp.async)
// ---------------------------------------------------------------------------
__device__ __forceinline__ uint32_t smem_u32(const void* p) {
    uint32_t a;
    asm("{ .reg .u64 t; cvta.to.shared.u64 t, %1; cvt.u32.u64 %0, t; }"
        : "=r"(a) : "l"(p));
    return a;
}
__device__ __forceinline__ void ldsm4(uint32_t* r, uint32_t addr) {
    asm volatile("ldmatrix.sync.aligned.m8n8.x4.shared.b16 {%0,%1,%2,%3}, [%4];"
                 : "=r"(r[0]), "=r"(r[1]), "=r"(r[2]), "=r"(r[3]) : "r"(addr));
}
__device__ __forceinline__ void ldsm4t(uint32_t* r, uint32_t addr) {
    asm volatile("ldmatrix.sync.aligned.m8n8.x4.trans.shared.b16 {%0,%1,%2,%3}, [%4];"
                 : "=r"(r[0]), "=r"(r[1]), "=r"(r[2]), "=r"(r[3]) : "r"(addr));
}
__device__ __forceinline__ void mma_bf16(float* c, const uint32_t* a,
                                         uint32_t b0, uint32_t b1) {
    asm volatile(
        "mma.sync.aligned.m16n8k16.row.col.f32.bf16.bf16.f32 "
        "{%0,%1,%2,%3}, {%4,%5,%6,%7}, {%8,%9}, {%0,%1,%2,%3};"
        : "+f"(c[0]), "+f"(c[1]), "+f"(c[2]), "+f"(c[3])
        : "r"(a[0]), "r"(a[1]), "r"(a[2]), "r"(a[3]), "r"(b0), "r"(b1));
}
__device__ __forceinline__ void cp16(uint32_t sdst, const void* gsrc) {
    asm volatile("cp.async.cg.shared.global [%0], [%1], 16;"
                 :: "r"(sdst), "l"(gsrc) : "memory");
}
#define CP_COMMIT() asm volatile("cp.async.commit_group;" ::: "memory")
#define CP_WAIT(n)  asm volatile("cp.async.wait_group %0;" :: "n"(n) : "memory")

__device__ __forceinline__ uint32_t packbf(float a, float b) {
    __nv_bfloat162 t = __floats2bfloat162_rn(a, b);
    return *reinterpret_cast<uint32_t*>(&t);
}
__device__ __forceinline__ uint32_t packh(__nv_bfloat16 a, __nv_bfloat16 b) {
    __nv_bfloat162 t = __halves2bfloat162(a, b);
    return *reinterpret_cast<uint32_t*>(&t);
}

// ---------------------------------------------------------------------------
// Prep kernels
// ---------------------------------------------------------------------------
__global__ void rope_table_kernel(float* __restrict__ cosT, float* __restrict__ sinT) {
    int idx = blockIdx.x * 256 + threadIdx.x;
    if (idx >= SEQ * HALFD) return;
    int s = idx / HALFD, i = idx - s * HALFD;
    float invf = expf(-((float)i) * (2.0f / (float)DM) * 9.210340371976184f);
    float c, sn;
    sincosf((float)s * invf, &sn, &c);
    cosT[idx] = c;
    sinT[idx] = sn;
}

__global__ void split_kernel(const float* __restrict__ in,
                             __nv_bfloat16* __restrict__ hi,
                             __nv_bfloat16* __restrict__ lo, int n2) {
    int i = blockIdx.x * 256 + threadIdx.x;
    if (i >= n2) return;
    float2 v = ((const float2*)in)[i];
    __nv_bfloat16 hx = __float2bfloat16(v.x), hy = __float2bfloat16(v.y);
    __nv_bfloat16 lx = __float2bfloat16(v.x - __bfloat162float(hx));
    __nv_bfloat16 ly = __float2bfloat16(v.y - __bfloat162float(hy));
    ((__nv_bfloat162*)hi)[i] = __halves2bfloat162(hx, hy);
    ((__nv_bfloat162*)lo)[i] = __halves2bfloat162(lx, ly);
}

// Fused 4-way W transpose+split; blockIdx.z selects the matrix.
__global__ void wsplit4_kernel(const float* __restrict__ Wq, const float* __restrict__ Wk,
                               const float* __restrict__ Wv, const float* __restrict__ Wo,
                               __nv_bfloat16* __restrict__ TThAll,
                               __nv_bfloat16* __restrict__ TTlAll) {
    __shared__ float t[32][33];
    const int z = blockIdx.z;
    const float* W = (z == 0) ? Wq : (z == 1) ? Wk : (z == 2) ? Wv : Wo;
    const size_t WSZ = (size_t)DM * DM;
    __nv_bfloat16* Th = TThAll + (size_t)z * WSZ;
    __nv_bfloat16* Tl = TTlAll + (size_t)z * WSZ;
    int bx = blockIdx.x << 5, by = blockIdx.y << 5;
    int x = threadIdx.x, y = threadIdx.y;
#pragma unroll
    for (int i = 0; i < 32; i += 8)
        t[y + i][x] = W[(size_t)(by + y + i) * DM + bx + x];
    __syncthreads();
#pragma unroll
    for (int i = 0; i < 32; i += 8) {
        float v = t[x][y + i];
        __nv_bfloat16 h = __float2bfloat16(v);
        size_t o = (size_t)(bx + y + i) * DM + by + x;
        Th[o] = h;
        Tl[o] = __float2bfloat16(v - __bfloat162float(h));
    }
}

#define NCHUNK (DM / 64)

// ---------------------------------------------------------------------------
// QKV GEMM — CTA tile 128x256, 512 threads, 16 warps (4m x 4n), warp 32x64.
// smem: (A 32KB + B 64KB) x 2 buffers = 192KB; 1 CTA/SM.
// ldsm:MMA ratio 4.0 (vs 3.0 at 32x32) -> smem crossbar ~67% at tensor peak.
// ---------------------------------------------------------------------------
#define QA_H 0
#define QA_L 16384
#define QB_H 32768
#define QB_L 65536
#define QBUF 98304
#define QKV_SMEM (2 * QBUF)  // 196608

#define QFILL(buf, c)                                                         \
    do {                                                                      \
        const uint32_t bb = sb + (buf) * QBUF;                                \
        const int kbB = (c) * 128;                                            \
        _Pragma("unroll")                                                     \
        for (int q = 0; q < 2; ++q) {                                         \
            uint32_t o = faoff + q * 16;                                      \
            uint32_t sw = o ^ ((o >> 3) & 0x70);                              \
            cp16(bb + QA_H + sw, pAh + kbB + q * 16);                         \
            cp16(bb + QA_L + sw, pAl + kbB + q * 16);                         \
        }                                                                     \
        _Pragma("unroll")                                                     \
        for (int q = 0; q < 4; ++q) {                                         \
            uint32_t o = fboff + q * 16;                                      \
            uint32_t sw = o ^ ((o >> 3) & 0x70);                              \
            cp16(bb + QB_H + sw, pBh + kbB + q * 16);                         \
            cp16(bb + QB_L + sw, pBl + kbB + q * 16);                         \
        }                                                                     \
    } while (0)

__global__ __launch_bounds__(512, 1)
void gemm_qkv(const __nv_bfloat16* __restrict__ Xh, const __nv_bfloat16* __restrict__ Xl,
              const __nv_bfloat16* __restrict__ WTh, const __nv_bfloat16* __restrict__ WTl,
              const float* __restrict__ bq, const float* __restrict__ bk,
              const float* __restrict__ bv,
              const float* __restrict__ cosT, const float* __restrict__ sinT,
              __nv_bfloat16* __restrict__ Qh, __nv_bfloat16* __restrict__ Ql,
              __nv_bfloat16* __restrict__ Kh, __nv_bfloat16* __restrict__ Kl,
              __nv_bfloat16* __restrict__ Vh, __nv_bfloat16* __restrict__ Vl)
{
    extern __shared__ char smc[];
    const uint32_t sb = smem_u32(smc);
    const int tid = threadIdx.x;
    const int wid = tid >> 5, lane = tid & 31;
    const int wm = wid & 3, wn = wid >> 2;   // 4 (m) x 4 (n), warp-tile 32x64
    const int pj = blockIdx.x / 3;
    const int col0 = (blockIdx.x - pj * 3) << 8;  // 256-wide N tile
    const int row0 = blockIdx.y << 7;
    const int lrow = lane & 15, lhi = (lane >> 4) << 4;

    const size_t WSZ = (size_t)DM * DM;
    const __nv_bfloat16* Bh = WTh + (size_t)pj * WSZ;
    const __nv_bfloat16* Bl = WTl + (size_t)pj * WSZ;
    const float* bias = (pj == 0) ? bq : (pj == 1) ? bk : bv;
    __nv_bfloat16* outH = (pj == 0) ? Qh : (pj == 1) ? Kh : Vh;
    __nv_bfloat16* outL = (pj == 0) ? Ql : (pj == 1) ? Kl : Vl;
    const int doRope = (pj < 2);
    const float scale = (pj == 0) ? 0.125f : 1.0f;

    float acc[2][8][4];
#pragma unroll
    for (int i = 0; i < 2; ++i)
#pragma unroll
        for (int j = 0; j < 8; ++j)
#pragma unroll
            for (int q = 0; q < 4; ++q) acc[i][j][q] = 0.f;

    // Fill: A 128 rows, 4 thr/row x 2 cp16; B 256 rows, 2 thr/row x 4 cp16
    const int farow = tid >> 2, facb = (tid & 3) << 5;
    const int fbrow = tid >> 1, fbcb = (tid & 1) << 6;
    const uint32_t faoff = farow * 128 + facb;
    const uint32_t fboff = fbrow * 128 + fbcb;
    const char* pAh = (const char*)(Xh + (size_t)(row0 + farow) * DM) + facb;
    const char* pAl = (const char*)(Xl + (size_t)(row0 + farow) * DM) + facb;
    const char* pBh = (const char*)(Bh + (size_t)(col0 + fbrow) * DM) + fbcb;
    const char* pBl = (const char*)(Bl + (size_t)(col0 + fbrow) * DM) + fbcb;

    QFILL(0, 0);
    CP_COMMIT();

    for (int c = 0; c < NCHUNK; ++c) {
        if (c + 1 < NCHUNK) {
            QFILL((c + 1) & 1, c + 1);
            CP_COMMIT();
            CP_WAIT(1);
        } else {
            CP_WAIT(0);
        }
        __syncthreads();
        const uint32_t base = sb + (c & 1) * QBUF;
#pragma unroll
        for (int kk = 0; kk < 4; ++kk) {
            uint32_t ahf[2][4], alf[2][4];
#pragma unroll
            for (int mi = 0; mi < 2; ++mi) {
                uint32_t o = (uint32_t)(wm * 32 + mi * 16 + lrow) * 128 + kk * 32 + lhi;
                uint32_t sw = o ^ ((o >> 3) & 0x70);
                ldsm4(ahf[mi], base + QA_H + sw);
                ldsm4(alf[mi], base + QA_L + sw);
            }
#pragma unroll
            for (int nt = 0; nt < 4; ++nt) {
                uint32_t bhf[4], blf[4];
                uint32_t o = (uint32_t)(wn * 64 + nt * 16 + lrow) * 128 + kk * 32 + lhi;
                uint32_t sw = o ^ ((o >> 3) & 0x70);
                ldsm4(bhf, base + QB_H + sw);
                ldsm4(blf, base + QB_L + sw);
#pragma unroll
                for (int mi = 0; mi < 2; ++mi)
#pragma unroll
                    for (int hb = 0; hb < 2; ++hb) {
                        float* a = acc[mi][nt * 2 + hb];
                        mma_bf16(a, ahf[mi], bhf[hb], bhf[hb + 2]);
                        mma_bf16(a, ahf[mi], blf[hb], blf[hb + 2]);
                        mma_bf16(a, alf[mi], bhf[hb], bhf[hb + 2]);
                    }
            }
        }
        __syncthreads();
    }

    const int qr = lane >> 2, qc = (lane & 3) << 1;
#pragma unroll
    for (int mi = 0; mi < 2; ++mi)
#pragma unroll
        for (int nj = 0; nj < 8; ++nj) {
            const int col = col0 + wn * 64 + nj * 8 + qc;
            const float b0 = __ldg(bias + col), b1 = __ldg(bias + col + 1);
#pragma unroll
            for (int hf = 0; hf < 2; ++hf) {
                const int grow = row0 + wm * 32 + mi * 16 + qr + hf * 8;
                float v0 = acc[mi][nj][hf * 2 + 0] + b0;
                float v1 = acc[mi][nj][hf * 2 + 1] + b1;
                if (doRope) {
                    const int srow = grow & (SEQ - 1);
                    const size_t ti = (size_t)srow * HALFD + (col >> 1);
                    const float cs = cosT[ti], sn = sinT[ti];
                    const float r0 = v0 * cs - v1 * sn;
                    const float r1 = v0 * sn + v1 * cs;
                    v0 = r0; v1 = r1;
                }
                v0 *= scale; v1 *= scale;
                __nv_bfloat16 h0 = __float2bfloat16(v0), h1 = __float2bfloat16(v1);
                *reinterpret_cast<uint32_t*>(outH + (size_t)grow * DM + col) = packh(h0, h1);
                *reinterpret_cast<uint32_t*>(outL + (size_t)grow * DM + col) =
                    packbf(v0 - __bfloat162float(h0), v1 - __bfloat162float(h1));
            }
        }
}

// ---------------------------------------------------------------------------
// O-projection GEMM — R14 config (CTA 128x128, 512 threads, warp 32x32)
// ---------------------------------------------------------------------------
#define TILE_B   16384
#define GBUF     (4 * TILE_B)
#define GEMM_SMEM (2 * GBUF)

#define GEMM_FILL(buf, c)                                                     \
    do {                                                                      \
        const uint32_t bb = sb + (buf) * GBUF;                                \
        const int kbB = (c) * 128;                                            \
        _Pragma("unroll")                                                     \
        for (int q = 0; q < 2; ++q) {                                         \
            uint32_t o = foff + q * 16;                                       \
            uint32_t sw = o ^ ((o >> 3) & 0x70);                              \
            cp16(bb + 0 * TILE_B + sw, pAh + kbB + q * 16);                   \
            cp16(bb + 1 * TILE_B + sw, pAl + kbB + q * 16);                   \
            cp16(bb + 2 * TILE_B + sw, pBh + kbB + q * 16);                   \
            cp16(bb + 3 * TILE_B + sw, pBl + kbB + q * 16);                   \
        }                                                                     \
    } while (0)

__global__ __launch_bounds__(512, 1)
void gemm_mma(const __nv_bfloat16* __restrict__ Ah, const __nv_bfloat16* __restrict__ Al,
              const __nv_bfloat16* __restrict__ Bh, const __nv_bfloat16* __restrict__ Bl,
              const float* __restrict__ bias, float* __restrict__ outF)
{
    extern __shared__ char smc[];
    const uint32_t sb = smem_u32(smc);
    const int tid = threadIdx.x;
    const int wid = tid >> 5, lane = tid & 31;
    const int wm = wid & 3, wn = wid >> 2;
    const int col0 = blockIdx.x << 7, row0 = blockIdx.y << 7;
    const int lrow = lane & 15, lhi = (lane >> 4) << 4;

    float acc[2][4][4];
#pragma unroll
    for (int i = 0; i < 2; ++i)
#pragma unroll
        for (int j = 0; j < 4; ++j)
#pragma unroll
            for (int q = 0; q < 4; ++q) acc[i][j][q] = 0.f;

    const int frow = tid >> 2;
    const int fcb = (tid & 3) << 5;
    const uint32_t foff = frow * 128 + fcb;
    const char* pAh = (const char*)(Ah + (size_t)(row0 + frow) * DM) + fcb;
    const char* pAl = (const char*)(Al + (size_t)(row0 + frow) * DM) + fcb;
    const char* pBh = (const char*)(Bh + (size_t)(col0 + frow) * DM) + fcb;
    const char* pBl = (const char*)(Bl + (size_t)(col0 + frow) * DM) + fcb;

    GEMM_FILL(0, 0);
    CP_COMMIT();
    for (int c = 0; c < NCHUNK; ++c) {
        if (c + 1 < NCHUNK) {
            GEMM_FILL((c + 1) & 1, c + 1);
            CP_COMMIT();
            CP_WAIT(1);
        } else {
            CP_WAIT(0);
        }
        __syncthreads();
        const uint32_t base = sb + (c & 1) * GBUF;
#pragma unroll
        for (int kk = 0; kk < 4; ++kk) {
            uint32_t ahf[2][4], alf[2][4], bhf[2][4], blf[2][4];
#pragma unroll
            for (int mi = 0; mi < 2; ++mi) {
                uint32_t o = (uint32_t)(wm * 32 + mi * 16 + lrow) * 128 + kk * 32 + lhi;
                uint32_t sw = o ^ ((o >> 3) & 0x70);
                ldsm4(ahf[mi], base + 0 * TILE_B + sw);
                ldsm4(alf[mi], base + 1 * TILE_B + sw);
            }
#pragma unroll
            for (int nt = 0; nt < 2; ++nt) {
                uint32_t o = (uint32_t)(wn * 32 + nt * 16 + lrow) * 128 + kk * 32 + lhi;
                uint32_t sw = o ^ ((o >> 3) & 0x70);
                ldsm4(bhf[nt], base + 2 * TILE_B + sw);
                ldsm4(blf[nt], base + 3 * TILE_B + sw);
            }
#pragma unroll
            for (int mi = 0; mi < 2; ++mi)
#pragma unroll
                for (int nj = 0; nj < 4; ++nj) {
                    const int nt = nj >> 1, hb = nj & 1;
                    mma_bf16(acc[mi][nj], ahf[mi], bhf[nt][hb], bhf[nt][hb + 2]);
                    mma_bf16(acc[mi][nj], ahf[mi], blf[nt][hb], blf[nt][hb + 2]);
                    mma_bf16(acc[mi][nj], alf[mi], bhf[nt][hb], bhf[nt][hb + 2]);
                }
        }
        __syncthreads();
    }

    const int qr = lane >> 2, qc = (lane & 3) << 1;
#pragma unroll
    for (int mi = 0; mi < 2; ++mi)
#pragma unroll
        for (int nj = 0; nj < 4; ++nj) {
            const int col = col0 + wn * 32 + nj * 8 + qc;
            const float b0 = __ldg(bias + col), b1 = __ldg(bias + col + 1);
#pragma unroll
            for (int hf = 0; hf < 2; ++hf) {
                const int grow = row0 + wm * 32 + mi * 16 + qr + hf * 8;
                *(float2*)(outF + (size_t)grow * DM + col) =
                    make_float2(acc[mi][nj][hf * 2 + 0] + b0,
                                acc[mi][nj][hf * 2 + 1] + b1);
            }
        }
}

// ---------------------------------------------------------------------------
// Flash attention via HMMA (unchanged — passing, 2 CTA/SM)
// ---------------------------------------------------------------------------
#define AQ_H 0
#define AQ_L 16384
#define ABUF0 32768
#define KVBUF 32768
#define BT_KH 0
#define BT_KL 8192
#define BT_VH 16384
#define BT_VL 24576
#define ATTN_SMEM (ABUF0 + 2 * KVBUF)  // 98304

__global__ __launch_bounds__(256, 2)
void attn_mma(const __nv_bfloat16* __restrict__ Qh, const __nv_bfloat16* __restrict__ Ql,
              const __nv_bfloat16* __restrict__ Kh, const __nv_bfloat16* __restrict__ Kl,
              const __nv_bfloat16* __restrict__ Vh, const __nv_bfloat16* __restrict__ Vl,
              __nv_bfloat16* __restrict__ Eh, __nv_bfloat16* __restrict__ El)
{
    extern __shared__ char smc[];
    const uint32_t sb = smem_u32(smc);
    const int tid = threadIdx.x, wq = tid >> 5, lane = tid & 31;
    const int bh = blockIdx.y, b = bh / NHEAD, h = bh - (bh / NHEAD) * NHEAD;
    const int qt = gridDim.x - 1 - blockIdx.x;  // heavy tiles first
    const int q0 = qt << 7;
    const int nch = 2 * qt + 2;
    const size_t base = (size_t)b * SEQ * DM + (size_t)h * HDIM;

    const int frow = tid >> 1, fcb = (tid & 1) << 6;
    uint32_t fsw[4];
#pragma unroll
    for (int q = 0; q < 4; ++q) {
        uint32_t o = (uint32_t)frow * 128 + fcb + q * 16;
        fsw[q] = o ^ ((o >> 3) & 0x70);
    }
    const int frow2 = tid >> 2, fcb2 = (tid & 3) << 5;
    uint32_t fsw2[2];
#pragma unroll
    for (int q = 0; q < 2; ++q) {
        uint32_t o = (uint32_t)frow2 * 128 + fcb2 + q * 16;
        fsw2[q] = o ^ ((o >> 3) & 0x70);
    }

    {
        const char* pQh = (const char*)(Qh + base + (size_t)(q0 + frow) * DM) + fcb;
        const char* pQl = (const char*)(Ql + base + (size_t)(q0 + frow) * DM) + fcb;
#pragma unroll
        for (int q = 0; q < 4; ++q) {
            cp16(sb + AQ_H + fsw[q], pQh + q * 16);
            cp16(sb + AQ_L + fsw[q], pQl + q * 16);
        }
    }
#define AFILL(bufbase, kb)                                                    \
    do {                                                                      \
        const char* pKh = (const char*)(Kh + base + (size_t)((kb) + frow2) * DM) + fcb2; \
        const char* pKl = (const char*)(Kl + base + (size_t)((kb) + frow2) * DM) + fcb2; \
        const char* pVh = (const char*)(Vh + base + (size_t)((kb) + frow2) * DM) + fcb2; \
        const char* pVl = (const char*)(Vl + base + (size_t)((kb) + frow2) * DM) + fcb2; \
        _Pragma("unroll")                                                     \
        for (int q = 0; q < 2; ++q) {                                         \
            cp16((bufbase) + BT_KH + fsw2[q], pKh + q * 16);                  \
            cp16((bufbase) + BT_KL + fsw2[q], pKl + q * 16);                  \
            cp16((bufbase) + BT_VH + fsw2[q], pVh + q * 16);                  \
            cp16((bufbase) + BT_VL + fsw2[q], pVl + q * 16);                  \
        }                                                                     \
    } while (0)

    AFILL(sb + ABUF0, 0);
    CP_COMMIT();
    CP_WAIT(0);
    __syncthreads();

    float m0 = -1e30f, m1 = -1e30f, l0 = 0.f, l1 = 0.f;
    float o_[8][4];
#pragma unroll
    for (int i = 0; i < 8; ++i)
#pragma unroll
        for (int j = 0; j < 4; ++j) o_[i][j] = 0.f;

    const int lrow = lane & 15, lhi = (lane >> 4) << 4;
    const int vrow = ((lane >> 3) & 1) * 8 + (lane & 7);
    const int vcol = (lane >> 4) << 4;

    for (int c = 0; c < nch; ++c) {
        const int kb = c << 6;
        if (c + 1 < nch) {
            AFILL(sb + ABUF0 + ((c + 1) & 1) * KVBUF, (c + 1) << 6);
            CP_COMMIT();
        }
        if (c > 0) {
            if (c + 1 < nch) { CP_WAIT(1); } else { CP_WAIT(0); }
        }
        __syncthreads();
        const uint32_t tb = sb + ABUF0 + (c & 1) * KVBUF;

        float s[8][4];
#pragma unroll
        for (int i = 0; i < 8; ++i)
#pragma unroll
            for (int j = 0; j < 4; ++j) s[i][j] = 0.f;

#pragma unroll
        for (int kk = 0; kk < 4; ++kk) {
            uint32_t aqh[4], aql[4];
            {
                uint32_t o = (uint32_t)(wq * 16 + lrow) * 128 + kk * 32 + lhi;
                uint32_t sw = o ^ ((o >> 3) & 0x70);
                ldsm4(aqh, sb + AQ_H + sw);
                ldsm4(aql, sb + AQ_L + sw);
            }
#pragma unroll
            for (int g = 0; g < 4; ++g) {
                uint32_t o = (uint32_t)(g * 16 + lrow) * 128 + kk * 32 + lhi;
                uint32_t sw = o ^ ((o >> 3) & 0x70);
                uint32_t kh[4], kl[4];
                ldsm4(kh, tb + BT_KH + sw);
                ldsm4(kl, tb + BT_KL + sw);
                mma_bf16(s[2 * g],     aqh, kh[0], kh[2]);
                mma_bf16(s[2 * g],     aqh, kl[0], kl[2]);
                mma_bf16(s[2 * g],     aql, kh[0], kh[2]);
                mma_bf16(s[2 * g + 1], aqh, kh[1], kh[3]);
                mma_bf16(s[2 * g + 1], aqh, kl[1], kl[3]);
                mma_bf16(s[2 * g + 1], aql, kh[1], kh[3]);
            }
        }

        const int dq = q0 - kb;
        if (dq < 128) {
            const int qr0 = wq * 16 + (lane >> 2);
            const int kbn = (lane & 3) << 1;
            const int th0 = qr0 + dq, th1 = qr0 + 8 + dq;
#pragma unroll
            for (int jb = 0; jb < 8; ++jb) {
                const int k0 = jb * 8 + kbn;
                if (k0 > th0)     s[jb][0] = -1e30f;
                if (k0 + 1 > th0) s[jb][1] = -1e30f;
                if (k0 > th1)     s[jb][2] = -1e30f;
                if (k0 + 1 > th1) s[jb][3] = -1e30f;
            }
        }

        float mx0 = -1e30f, mx1 = -1e30f;
#pragma unroll
        for (int jb = 0; jb < 8; ++jb) {
            mx0 = fmaxf(mx0, fmaxf(s[jb][0], s[jb][1]));
            mx1 = fmaxf(mx1, fmaxf(s[jb][2], s[jb][3]));
        }
        mx0 = fmaxf(mx0, __shfl_xor_sync(0xffffffffu, mx0, 1));
        mx0 = fmaxf(mx0, __shfl_xor_sync(0xffffffffu, mx0, 2));
        mx1 = fmaxf(mx1, __shfl_xor_sync(0xffffffffu, mx1, 1));
        mx1 = fmaxf(mx1, __shfl_xor_sync(0xffffffffu, mx1, 2));
        const float mn0 = fmaxf(m0, mx0), mn1 = fmaxf(m1, mx1);
        const float c0 = __expf(m0 - mn0), c1 = __expf(m1 - mn1);
        float sum0 = 0.f, sum1 = 0.f;
#pragma unroll
        for (int jb = 0; jb < 8; ++jb) {
            s[jb][0] = __expf(s[jb][0] - mn0);
            s[jb][1] = __expf(s[jb][1] - mn0);
            s[jb][2] = __expf(s[jb][2] - mn1);
            s[jb][3] = __expf(s[jb][3] - mn1);
            sum0 += s[jb][0] + s[jb][1];
            sum1 += s[jb][2] + s[jb][3];
        }
        sum0 += __shfl_xor_sync(0xffffffffu, sum0, 1);
        sum0 += __shfl_xor_sync(0xffffffffu, sum0, 2);
        sum1 += __shfl_xor_sync(0xffffffffu, sum1, 1);
        sum1 += __shfl_xor_sync(0xffffffffu, sum1, 2);
        l0 = l0 * c0 + sum0;
        l1 = l1 * c1 + sum1;
        m0 = mn0; m1 = mn1;
#pragma unroll
        for (int db = 0; db < 8; ++db) {
            o_[db][0] *= c0; o_[db][1] *= c0;
            o_[db][2] *= c1; o_[db][3] *= c1;
        }

#pragma unroll
        for (int t = 0; t < 4; ++t) {
            uint32_t pah[4], pal[4];
            {
                const float f0 = s[2 * t][0], f1 = s[2 * t][1];
                const float f2 = s[2 * t][2], f3 = s[2 * t][3];
                __nv_bfloat16 h0 = __float2bfloat16(f0), h1 = __float2bfloat16(f1);
                __nv_bfloat16 h2 = __float2bfloat16(f2), h3 = __float2bfloat16(f3);
                pah[0] = packh(h0, h1);
                pah[1] = packh(h2, h3);
                pal[0] = packbf(f0 - __bfloat162float(h0), f1 - __bfloat162float(h1));
                pal[1] = packbf(f2 - __bfloat162float(h2), f3 - __bfloat162float(h3));
            }
            {
                const float f0 = s[2 * t + 1][0], f1 = s[2 * t + 1][1];
                const float f2 = s[2 * t + 1][2], f3 = s[2 * t + 1][3];
                __nv_bfloat16 h0 = __float2bfloat16(f0), h1 = __float2bfloat16(f1);
                __nv_bfloat16 h2 = __float2bfloat16(f2), h3 = __float2bfloat16(f3);
                pah[2] = packh(h0, h1);
                pah[3] = packh(h2, h3);
                pal[2] = packbf(f0 - __bfloat162float(h0), f1 - __bfloat162float(h1));
                pal[3] = packbf(f2 - __bfloat162float(h2), f3 - __bfloat162float(h3));
            }
#pragma unroll
            for (int g = 0; g < 4; ++g) {
                uint32_t o = (uint32_t)(t * 16 + vrow) * 128 + g * 32 + vcol;
                uint32_t sw = o ^ ((o >> 3) & 0x70);
                uint32_t vh[4], vl[4];
                ldsm4t(vh, tb + BT_VH + sw);
                ldsm4t(vl, tb + BT_VL + sw);
                mma_bf16(o_[2 * g],     pah, vh[0], vh[1]);
                mma_bf16(o_[2 * g],     pal, vh[0], vh[1]);
                mma_bf16(o_[2 * g],     pah, vl[0], vl[1]);
                mma_bf16(o_[2 * g + 1], pah, vh[2], vh[3]);
                mma_bf16(o_[2 * g + 1], pal, vh[2], vh[3]);
                mma_bf16(o_[2 * g + 1], pah, vl[2], vl[3]);
            }
        }
        __syncthreads();
    }

    const float inv0 = 1.0f / l0, inv1 = 1.0f / l1;
    const int r0g = q0 + wq * 16 + (lane >> 2);
    const size_t ro0 = base + (size_t)r0g * DM;
    const size_t ro1 = ro0 + (size_t)8 * DM;
    const int cb = (lane & 3) << 1;
#pragma unroll
    for (int db = 0; db < 8; ++db) {
        const int col = db * 8 + cb;
        {
            const float f0 = o_[db][0] * inv0, f1 = o_[db][1] * inv0;
            __nv_bfloat16 h0 = __float2bfloat16(f0), h1 = __float2bfloat16(f1);
            *reinterpret_cast<uint32_t*>(Eh + ro0 + col) = packh(h0, h1);
            *reinterpret_cast<uint32_t*>(El + ro0 + col) =
                packbf(f0 - __bfloat162float(h0), f1 - __bfloat162float(h1));
        }
        {
            const float f2 = o_[db][2] * inv1, f3 = o_[db][3] * inv1;
            __nv_bfloat16 h2 = __float2bfloat16(f2), h3 = __float2bfloat16(f3);
            *reinterpret_cast<uint32_t*>(Eh + ro1 + col) = packh(h2, h3);
            *reinterpret_cast<uint32_t*>(El + ro1 + col) =
                packbf(f2 - __bfloat162float(h2), f3 - __bfloat162float(h3));
        }
    }
}

// ---------------------------------------------------------------------------
// Launch
// ---------------------------------------------------------------------------
extern "C" void kernel_launch(void* const* d_in, const int* in_sizes, int n_in,
                              void* d_out, int out_size)
{
    const float* X  = (const float*)d_in[0];
    const float* Wq = (const float*)d_in[1];
    const float* bq = (const float*)d_in[2];
    const float* Wk = (const float*)d_in[3];
    const float* bk = (const float*)d_in[4];
    const float* Wv = (const float*)d_in[5];
    const float* bv = (const float*)d_in[6];
    const float* Wo = (const float*)d_in[7];
    const float* bo = (const float*)d_in[8];
    float* out = (float*)d_out;

    float *cosT, *sinT;
    __nv_bfloat16 *Qh, *Ql, *Kh, *Kl, *Vh, *Vl, *Eh, *El, *Xh, *Xl, *WTh, *WTl;
    cudaGetSymbolAddress((void**)&cosT, g_cosT);
    cudaGetSymbolAddress((void**)&sinT, g_sinT);
    cudaGetSymbolAddress((void**)&Qh, g_Qh);
    cudaGetSymbolAddress((void**)&Ql, g_Ql);
    cudaGetSymbolAddress((void**)&Kh, g_Kh);
    cudaGetSymbolAddress((void**)&Kl, g_Kl);
    cudaGetSymbolAddress((void**)&Vh, g_Vh);
    cudaGetSymbolAddress((void**)&Vl, g_Vl);
    cudaGetSymbolAddress((void**)&Eh, g_Eh);
    cudaGetSymbolAddress((void**)&El, g_El);
    cudaGetSymbolAddress((void**)&Xh, g_Xh);
    cudaGetSymbolAddress((void**)&Xl, g_Xl);
    cudaGetSymbolAddress((void**)&WTh, g_WTh);
    cudaGetSymbolAddress((void**)&WTl, g_WTl);

    cudaFuncSetAttribute(gemm_qkv, cudaFuncAttributeMaxDynamicSharedMemorySize, QKV_SMEM);
    cudaFuncSetAttribute(gemm_mma, cudaFuncAttributeMaxDynamicSharedMemorySize, GEMM_SMEM);
    cudaFuncSetAttribute(attn_mma, cudaFuncAttributeMaxDynamicSharedMemorySize, ATTN_SMEM);

    const size_t WSZ = (size_t)DM * DM;

    rope_table_kernel<<<(SEQ * HALFD + 255) / 256, 256>>>(cosT, sinT);

    wsplit4_kernel<<<dim3(DM / 32, DM / 32, 4), dim3(32, 8)>>>(
        Wq, Wk, Wv, Wo, WTh, WTl);

    const int NP = MTOT * DM / 2;
    split_kernel<<<(NP + 255) / 256, 256>>>(X, Xh, Xl, NP);

    gemm_qkv<<<dim3(9, MTOT / 128), 512, QKV_SMEM>>>(
        Xh, Xl, WTh, WTl, bq, bk, bv, cosT, sinT, Qh, Ql, Kh, Kl, Vh, Vl);

    attn_mma<<<dim3(SEQ / 128, BATCH * NHEAD), 256, ATTN_SMEM>>>(Qh, Ql, Kh, Kl,
                                                                 Vh, Vl, Eh, El);

    gemm_mma<<<dim3(DM / 128, MTOT / 128), 512, GEMM_SMEM>>>(
        Eh, El, WTh + 3 * WSZ, WTl + 3 * WSZ, bo, out);
}

// round 17
// speedup vs baseline: 1.0854x; 1.0508x over previous
#include <cuda_runtime.h>
#include <cuda_bf16.h>
#include <math.h>
#include <stdint.h>

#define NHEAD 12
#define HDIM  64
#define DM    768
#define SEQ   2048
#define BATCH 4
#define MTOT  (BATCH * SEQ)
#define HALFD 384

// ---------------------------------------------------------------------------
// Scratch (allocation-free rule: __device__ globals)
// ---------------------------------------------------------------------------
__device__ __nv_bfloat16 g_Qh[(size_t)MTOT * DM];
__device__ __nv_bfloat16 g_Ql[(size_t)MTOT * DM];
__device__ __nv_bfloat16 g_Kh[(size_t)MTOT * DM];
__device__ __nv_bfloat16 g_Kl[(size_t)MTOT * DM];
__device__ __nv_bfloat16 g_Vh[(size_t)MTOT * DM];
__device__ __nv_bfloat16 g_Vl[(size_t)MTOT * DM];
__device__ __nv_bfloat16 g_Eh[(size_t)MTOT * DM];
__device__ __nv_bfloat16 g_El[(size_t)MTOT * DM];
__device__ __nv_bfloat16 g_Xh[(size_t)MTOT * DM];
__device__ __nv_bfloat16 g_Xl[(size_t)MTOT * DM];
__device__ __nv_bfloat16 g_WTh[(size_t)4 * DM * DM];
__device__ __nv_bfloat16 g_WTl[(size_t)4 * DM * DM];
__device__ float g_cosT[(size_t)SEQ * HALFD];
__device__ float g_sinT[(size_t)SEQ * HALFD];

// ---------------------------------------------------------------------------
// Arch-neutral PTX helpers (mma.sync / ldmatrix / cp.async)
// ---------------------------------------------------------------------------
__device__ __forceinline__ uint32_t smem_u32(const void* p) {
    uint32_t a;
    asm("{ .reg .u64 t; cvta.to.shared.u64 t, %1; cvt.u32.u64 %0, t; }"
        : "=r"(a) : "l"(p));
    return a;
}
__device__ __forceinline__ void ldsm4(uint32_t* r, uint32_t addr) {
    asm volatile("ldmatrix.sync.aligned.m8n8.x4.shared.b16 {%0,%1,%2,%3}, [%4];"
                 : "=r"(r[0]), "=r"(r[1]), "=r"(r[2]), "=r"(r[3]) : "r"(addr));
}
__device__ __forceinline__ void ldsm4t(uint32_t* r, uint32_t addr) {
    asm volatile("ldmatrix.sync.aligned.m8n8.x4.trans.shared.b16 {%0,%1,%2,%3}, [%4];"
                 : "=r"(r[0]), "=r"(r[1]), "=r"(r[2]), "=r"(r[3]) : "r"(addr));
}
__device__ __forceinline__ void mma_bf16(float* c, const uint32_t* a,
                                         uint32_t b0, uint32_t b1) {
    asm volatile(
        "mma.sync.aligned.m16n8k16.row.col.f32.bf16.bf16.f32 "
        "{%0,%1,%2,%3}, {%4,%5,%6,%7}, {%8,%9}, {%0,%1,%2,%3};"
        : "+f"(c[0]), "+f"(c[1]), "+f"(c[2]), "+f"(c[3])
        : "r"(a[0]), "r"(a[1]), "r"(a[2]), "r"(a[3]), "r"(b0), "r"(b1));
}
__device__ __forceinline__ void cp16(uint32_t sdst, const void* gsrc) {
    asm volatile("cp.async.cg.shared.global [%0], [%1], 16;"
                 :: "r"(sdst), "l"(gsrc) : "memory");
}
#define CP_COMMIT() asm volatile("cp.async.commit_group;" ::: "memory")
#define CP_WAIT(n)  asm volatile("cp.async.wait_group %0;" :: "n"(n) : "memory")

__device__ __forceinline__ uint32_t packbf(float a, float b) {
    __nv_bfloat162 t = __floats2bfloat162_rn(a, b);
    return *reinterpret_cast<uint32_t*>(&t);
}
__device__ __forceinline__ uint32_t packh(__nv_bfloat16 a, __nv_bfloat16 b) {
    __nv_bfloat162 t = __halves2bfloat162(a, b);
    return *reinterpret_cast<uint32_t*>(&t);
}

// ---------------------------------------------------------------------------
// Prep kernels
// ---------------------------------------------------------------------------
__global__ void rope_table_kernel(float* __restrict__ cosT, float* __restrict__ sinT) {
    int idx = blockIdx.x * 256 + threadIdx.x;
    if (idx >= SEQ * HALFD) return;
    int s = idx / HALFD, i = idx - s * HALFD;
    float invf = expf(-((float)i) * (2.0f / (float)DM) * 9.210340371976184f);
    float c, sn;
    sincosf((float)s * invf, &sn, &c);
    cosT[idx] = c;
    sinT[idx] = sn;
}

__global__ void split_kernel(const float* __restrict__ in,
                             __nv_bfloat16* __restrict__ hi,
                             __nv_bfloat16* __restrict__ lo, int n2) {
    int i = blockIdx.x * 256 + threadIdx.x;
    if (i >= n2) return;
    float2 v = ((const float2*)in)[i];
    __nv_bfloat16 hx = __float2bfloat16(v.x), hy = __float2bfloat16(v.y);
    __nv_bfloat16 lx = __float2bfloat16(v.x - __bfloat162float(hx));
    __nv_bfloat16 ly = __float2bfloat16(v.y - __bfloat162float(hy));
    ((__nv_bfloat162*)hi)[i] = __halves2bfloat162(hx, hy);
    ((__nv_bfloat162*)lo)[i] = __halves2bfloat162(lx, ly);
}

// Fused 4-way W transpose+split; blockIdx.z selects the matrix.
__global__ void wsplit4_kernel(const float* __restrict__ Wq, const float* __restrict__ Wk,
                               const float* __restrict__ Wv, const float* __restrict__ Wo,
                               __nv_bfloat16* __restrict__ TThAll,
                               __nv_bfloat16* __restrict__ TTlAll) {
    __shared__ float t[32][33];
    const int z = blockIdx.z;
    const float* W = (z == 0) ? Wq : (z == 1) ? Wk : (z == 2) ? Wv : Wo;
    const size_t WSZ = (size_t)DM * DM;
    __nv_bfloat16* Th = TThAll + (size_t)z * WSZ;
    __nv_bfloat16* Tl = TTlAll + (size_t)z * WSZ;
    int bx = blockIdx.x << 5, by = blockIdx.y << 5;
    int x = threadIdx.x, y = threadIdx.y;
#pragma unroll
    for (int i = 0; i < 32; i += 8)
        t[y + i][x] = W[(size_t)(by + y + i) * DM + bx + x];
    __syncthreads();
#pragma unroll
    for (int i = 0; i < 32; i += 8) {
        float v = t[x][y + i];
        __nv_bfloat16 h = __float2bfloat16(v);
        size_t o = (size_t)(bx + y + i) * DM + by + x;
        Th[o] = h;
        Tl[o] = __float2bfloat16(v - __bfloat162float(h));
    }
}

// ---------------------------------------------------------------------------
// HMMA bf16-split GEMM cores — R14 config (CTA 128x128, 512 threads, 16 warps,
// warp-tile 32x32) upgraded to a 3-stage cp.async pipeline:
//   one barrier per chunk; fill(c+2) overlaps compute(c); buffer (c+2)%3 is
//   the one the barrier just retired, so no trailing sync is needed.
// smem: 3 x 64KB = 192KB, 1 CTA/SM.
// ---------------------------------------------------------------------------
#define TILE_B   16384
#define GBUF     (4 * TILE_B)
#define GEMM_SMEM (3 * GBUF)   // 196608
#define NCHUNK   (DM / 64)
#define GTHREADS 512

// 512-thread fill: 4 threads/row, 2x16B each per tile
#define GEMM_FILL(buf, c)                                                     \
    do {                                                                      \
        const uint32_t bb = sb + (uint32_t)(buf) * GBUF;                      \
        const int kbB = (c) * 128;                                            \
        _Pragma("unroll")                                                     \
        for (int q = 0; q < 2; ++q) {                                         \
            uint32_t o = foff + q * 16;                                       \
            uint32_t sw = o ^ ((o >> 3) & 0x70);                              \
            cp16(bb + 0 * TILE_B + sw, pAh + kbB + q * 16);                   \
            cp16(bb + 1 * TILE_B + sw, pAl + kbB + q * 16);                   \
            cp16(bb + 2 * TILE_B + sw, pBh + kbB + q * 16);                   \
            cp16(bb + 3 * TILE_B + sw, pBl + kbB + q * 16);                   \
        }                                                                     \
    } while (0)

// 3-stage mainloop: prologue fills buffers 0,1; per-iter one barrier.
#define GEMM_MAINLOOP()                                                       \
    GEMM_FILL(0, 0);                                                          \
    CP_COMMIT();                                                              \
    GEMM_FILL(1, 1);                                                          \
    CP_COMMIT();                                                              \
    {                                                                         \
        int cbuf = 0, fbuf = 2;                                               \
        for (int c = 0; c < NCHUNK; ++c) {                                    \
            if (c + 1 < NCHUNK) { CP_WAIT(1); } else { CP_WAIT(0); }          \
            __syncthreads();                                                  \
            if (c + 2 < NCHUNK) {                                             \
                GEMM_FILL(fbuf, c + 2);                                       \
                CP_COMMIT();                                                  \
                fbuf = (fbuf == 2) ? 0 : fbuf + 1;                            \
            }                                                                 \
            const uint32_t base = sb + (uint32_t)cbuf * GBUF;                 \
            cbuf = (cbuf == 2) ? 0 : cbuf + 1;                                \
            _Pragma("unroll")                                                 \
            for (int kk = 0; kk < 4; ++kk) {                                  \
                uint32_t ahf[2][4], alf[2][4], bhf[2][4], blf[2][4];          \
                _Pragma("unroll")                                             \
                for (int mi = 0; mi < 2; ++mi) {                              \
                    uint32_t o = (uint32_t)(wm * 32 + mi * 16 + lrow) * 128 + kk * 32 + lhi; \
                    uint32_t sw = o ^ ((o >> 3) & 0x70);                      \
                    ldsm4(ahf[mi], base + 0 * TILE_B + sw);                   \
                    ldsm4(alf[mi], base + 1 * TILE_B + sw);                   \
                }                                                             \
                _Pragma("unroll")                                             \
                for (int nt = 0; nt < 2; ++nt) {                              \
                    uint32_t o = (uint32_t)(wn * 32 + nt * 16 + lrow) * 128 + kk * 32 + lhi; \
                    uint32_t sw = o ^ ((o >> 3) & 0x70);                      \
                    ldsm4(bhf[nt], base + 2 * TILE_B + sw);                   \
                    ldsm4(blf[nt], base + 3 * TILE_B + sw);                   \
                }                                                             \
                _Pragma("unroll")                                             \
                for (int mi = 0; mi < 2; ++mi)                                \
                    _Pragma("unroll")                                         \
                    for (int nj = 0; nj < 4; ++nj) {                          \
                        const int nt = nj >> 1, hb = nj & 1;                  \
                        mma_bf16(acc[mi][nj], ahf[mi], bhf[nt][hb], bhf[nt][hb + 2]); \
                        mma_bf16(acc[mi][nj], ahf[mi], blf[nt][hb], blf[nt][hb + 2]); \
                        mma_bf16(acc[mi][nj], alf[mi], bhf[nt][hb], bhf[nt][hb + 2]); \
                    }                                                         \
            }                                                                 \
        }                                                                     \
    }

// Fused QKV projection: grid (18, 64), 512 threads
__global__ __launch_bounds__(GTHREADS, 1)
void gemm_qkv(const __nv_bfloat16* __restrict__ Xh, const __nv_bfloat16* __restrict__ Xl,
              const __nv_bfloat16* __restrict__ WTh, const __nv_bfloat16* __restrict__ WTl,
              const float* __restrict__ bq, const float* __restrict__ bk,
              const float* __restrict__ bv,
              const float* __restrict__ cosT, const float* __restrict__ sinT,
              __nv_bfloat16* __restrict__ Qh, __nv_bfloat16* __restrict__ Ql,
              __nv_bfloat16* __restrict__ Kh, __nv_bfloat16* __restrict__ Kl,
              __nv_bfloat16* __restrict__ Vh, __nv_bfloat16* __restrict__ Vl)
{
    extern __shared__ char smc[];
    const uint32_t sb = smem_u32(smc);
    const int tid = threadIdx.x;
    const int wid = tid >> 5, lane = tid & 31;
    const int wm = wid & 3, wn = wid >> 2;   // 4 (m) x 4 (n) warp grid
    const int pj = blockIdx.x / 6;
    const int col0 = (blockIdx.x - pj * 6) << 7;
    const int row0 = blockIdx.y << 7;
    const int lrow = lane & 15, lhi = (lane >> 4) << 4;

    const size_t WSZ = (size_t)DM * DM;
    const __nv_bfloat16* Bh = WTh + (size_t)pj * WSZ;
    const __nv_bfloat16* Bl = WTl + (size_t)pj * WSZ;
    const float* bias = (pj == 0) ? bq : (pj == 1) ? bk : bv;
    __nv_bfloat16* outH = (pj == 0) ? Qh : (pj == 1) ? Kh : Vh;
    __nv_bfloat16* outL = (pj == 0) ? Ql : (pj == 1) ? Kl : Vl;
    const int doRope = (pj < 2);
    const float scale = (pj == 0) ? 0.125f : 1.0f;

    float acc[2][4][4];
#pragma unroll
    for (int i = 0; i < 2; ++i)
#pragma unroll
        for (int j = 0; j < 4; ++j)
#pragma unroll
            for (int q = 0; q < 4; ++q) acc[i][j][q] = 0.f;

    const int frow = tid >> 2;
    const int fcb = (tid & 3) << 5;
    const uint32_t foff = frow * 128 + fcb;
    const char* pAh = (const char*)(Xh + (size_t)(row0 + frow) * DM) + fcb;
    const char* pAl = (const char*)(Xl + (size_t)(row0 + frow) * DM) + fcb;
    const char* pBh = (const char*)(Bh + (size_t)(col0 + frow) * DM) + fcb;
    const char* pBl = (const char*)(Bl + (size_t)(col0 + frow) * DM) + fcb;

    GEMM_MAINLOOP();

    const int qr = lane >> 2, qc = (lane & 3) << 1;
#pragma unroll
    for (int mi = 0; mi < 2; ++mi)
#pragma unroll
        for (int nj = 0; nj < 4; ++nj) {
            const int col = col0 + wn * 32 + nj * 8 + qc;
            const float b0 = __ldg(bias + col), b1 = __ldg(bias + col + 1);
#pragma unroll
            for (int hf = 0; hf < 2; ++hf) {
                const int grow = row0 + wm * 32 + mi * 16 + qr + hf * 8;
                float v0 = acc[mi][nj][hf * 2 + 0] + b0;
                float v1 = acc[mi][nj][hf * 2 + 1] + b1;
                if (doRope) {
                    const int srow = grow & (SEQ - 1);
                    const size_t ti = (size_t)srow * HALFD + (col >> 1);
                    const float cs = cosT[ti], sn = sinT[ti];
                    const float r0 = v0 * cs - v1 * sn;
                    const float r1 = v0 * sn + v1 * cs;
                    v0 = r0; v1 = r1;
                }
                v0 *= scale; v1 *= scale;
                __nv_bfloat16 h0 = __float2bfloat16(v0), h1 = __float2bfloat16(v1);
                *reinterpret_cast<uint32_t*>(outH + (size_t)grow * DM + col) = packh(h0, h1);
                *reinterpret_cast<uint32_t*>(outL + (size_t)grow * DM + col) =
                    packbf(v0 - __bfloat162float(h0), v1 - __bfloat162float(h1));
            }
        }
}

// Output projection (fp32 out), 512 threads
__global__ __launch_bounds__(GTHREADS, 1)
void gemm_mma(const __nv_bfloat16* __restrict__ Ah, const __nv_bfloat16* __restrict__ Al,
              const __nv_bfloat16* __restrict__ Bh, const __nv_bfloat16* __restrict__ Bl,
              const float* __restrict__ bias, float* __restrict__ outF)
{
    extern __shared__ char smc[];
    const uint32_t sb = smem_u32(smc);
    const int tid = threadIdx.x;
    const int wid = tid >> 5, lane = tid & 31;
    const int wm = wid & 3, wn = wid >> 2;
    const int col0 = blockIdx.x << 7, row0 = blockIdx.y << 7;
    const int lrow = lane & 15, lhi = (lane >> 4) << 4;

    float acc[2][4][4];
#pragma unroll
    for (int i = 0; i < 2; ++i)
#pragma unroll
        for (int j = 0; j < 4; ++j)
#pragma unroll
            for (int q = 0; q < 4; ++q) acc[i][j][q] = 0.f;

    const int frow = tid >> 2;
    const int fcb = (tid & 3) << 5;
    const uint32_t foff = frow * 128 + fcb;
    const char* pAh = (const char*)(Ah + (size_t)(row0 + frow) * DM) + fcb;
    const char* pAl = (const char*)(Al + (size_t)(row0 + frow) * DM) + fcb;
    const char* pBh = (const char*)(Bh + (size_t)(col0 + frow) * DM) + fcb;
    const char* pBl = (const char*)(Bl + (size_t)(col0 + frow) * DM) + fcb;

    GEMM_MAINLOOP();

    const int qr = lane >> 2, qc = (lane & 3) << 1;
#pragma unroll
    for (int mi = 0; mi < 2; ++mi)
#pragma unroll
        for (int nj = 0; nj < 4; ++nj) {
            const int col = col0 + wn * 32 + nj * 8 + qc;
            const float b0 = __ldg(bias + col), b1 = __ldg(bias + col + 1);
#pragma unroll
            for (int hf = 0; hf < 2; ++hf) {
                const int grow = row0 + wm * 32 + mi * 16 + qr + hf * 8;
                *(float2*)(outF + (size_t)grow * DM + col) =
                    make_float2(acc[mi][nj][hf * 2 + 0] + b0,
                                acc[mi][nj][hf * 2 + 1] + b1);
            }
        }
}

// ---------------------------------------------------------------------------
// Flash attention via HMMA (unchanged — passing, 2 CTA/SM)
// ---------------------------------------------------------------------------
#define AQ_H 0
#define AQ_L 16384
#define ABUF0 32768
#define KVBUF 32768
#define BT_KH 0
#define BT_KL 8192
#define BT_VH 16384
#define BT_VL 24576
#define ATTN_SMEM (ABUF0 + 2 * KVBUF)  // 98304

__global__ __launch_bounds__(256, 2)
void attn_mma(const __nv_bfloat16* __restrict__ Qh, const __nv_bfloat16* __restrict__ Ql,
              const __nv_bfloat16* __restrict__ Kh, const __nv_bfloat16* __restrict__ Kl,
              const __nv_bfloat16* __restrict__ Vh, const __nv_bfloat16* __restrict__ Vl,
              __nv_bfloat16* __restrict__ Eh, __nv_bfloat16* __restrict__ El)
{
    extern __shared__ char smc[];
    const uint32_t sb = smem_u32(smc);
    const int tid = threadIdx.x, wq = tid >> 5, lane = tid & 31;
    const int bh = blockIdx.y, b = bh / NHEAD, h = bh - (bh / NHEAD) * NHEAD;
    const int qt = gridDim.x - 1 - blockIdx.x;  // heavy tiles first
    const int q0 = qt << 7;
    const int nch = 2 * qt + 2;
    const size_t base = (size_t)b * SEQ * DM + (size_t)h * HDIM;

    const int frow = tid >> 1, fcb = (tid & 1) << 6;
    uint32_t fsw[4];
#pragma unroll
    for (int q = 0; q < 4; ++q) {
        uint32_t o = (uint32_t)frow * 128 + fcb + q * 16;
        fsw[q] = o ^ ((o >> 3) & 0x70);
    }
    const int frow2 = tid >> 2, fcb2 = (tid & 3) << 5;
    uint32_t fsw2[2];
#pragma unroll
    for (int q = 0; q < 2; ++q) {
        uint32_t o = (uint32_t)frow2 * 128 + fcb2 + q * 16;
        fsw2[q] = o ^ ((o >> 3) & 0x70);
    }

    {
        const char* pQh = (const char*)(Qh + base + (size_t)(q0 + frow) * DM) + fcb;
        const char* pQl = (const char*)(Ql + base + (size_t)(q0 + frow) * DM) + fcb;
#pragma unroll
        for (int q = 0; q < 4; ++q) {
            cp16(sb + AQ_H + fsw[q], pQh + q * 16);
            cp16(sb + AQ_L + fsw[q], pQl + q * 16);
        }
    }
#define AFILL(bufbase, kb)                                                    \
    do {                                                                      \
        const char* pKh = (const char*)(Kh + base + (size_t)((kb) + frow2) * DM) + fcb2; \
        const char* pKl = (const char*)(Kl + base + (size_t)((kb) + frow2) * DM) + fcb2; \
        const char* pVh = (const char*)(Vh + base + (size_t)((kb) + frow2) * DM) + fcb2; \
        const char* pVl = (const char*)(Vl + base + (size_t)((kb) + frow2) * DM) + fcb2; \
        _Pragma("unroll")                                                     \
        for (int q = 0; q < 2; ++q) {                                         \
            cp16((bufbase) + BT_KH + fsw2[q], pKh + q * 16);                  \
            cp16((bufbase) + BT_KL + fsw2[q], pKl + q * 16);                  \
            cp16((bufbase) + BT_VH + fsw2[q], pVh + q * 16);                  \
            cp16((bufbase) + BT_VL + fsw2[q], pVl + q * 16);                  \
        }                                                                     \
    } while (0)

    AFILL(sb + ABUF0, 0);
    CP_COMMIT();
    CP_WAIT(0);
    __syncthreads();

    float m0 = -1e30f, m1 = -1e30f, l0 = 0.f, l1 = 0.f;
    float o_[8][4];
#pragma unroll
    for (int i = 0; i < 8; ++i)
#pragma unroll
        for (int j = 0; j < 4; ++j) o_[i][j] = 0.f;

    const int lrow = lane & 15, lhi = (lane >> 4) << 4;
    const int vrow = ((lane >> 3) & 1) * 8 + (lane & 7);
    const int vcol = (lane >> 4) << 4;

    for (int c = 0; c < nch; ++c) {
        const int kb = c << 6;
        if (c + 1 < nch) {
            AFILL(sb + ABUF0 + ((c + 1) & 1) * KVBUF, (c + 1) << 6);
            CP_COMMIT();
        }
        if (c > 0) {
            if (c + 1 < nch) { CP_WAIT(1); } else { CP_WAIT(0); }
        }
        __syncthreads();
        const uint32_t tb = sb + ABUF0 + (c & 1) * KVBUF;

        float s[8][4];
#pragma unroll
        for (int i = 0; i < 8; ++i)
#pragma unroll
            for (int j = 0; j < 4; ++j) s[i][j] = 0.f;

#pragma unroll
        for (int kk = 0; kk < 4; ++kk) {
            uint32_t aqh[4], aql[4];
            {
                uint32_t o = (uint32_t)(wq * 16 + lrow) * 128 + kk * 32 + lhi;
                uint32_t sw = o ^ ((o >> 3) & 0x70);
                ldsm4(aqh, sb + AQ_H + sw);
                ldsm4(aql, sb + AQ_L + sw);
            }
#pragma unroll
            for (int g = 0; g < 4; ++g) {
                uint32_t o = (uint32_t)(g * 16 + lrow) * 128 + kk * 32 + lhi;
                uint32_t sw = o ^ ((o >> 3) & 0x70);
                uint32_t kh[4], kl[4];
                ldsm4(kh, tb + BT_KH + sw);
                ldsm4(kl, tb + BT_KL + sw);
                mma_bf16(s[2 * g],     aqh, kh[0], kh[2]);
                mma_bf16(s[2 * g],     aqh, kl[0], kl[2]);
                mma_bf16(s[2 * g],     aql, kh[0], kh[2]);
                mma_bf16(s[2 * g + 1], aqh, kh[1], kh[3]);
                mma_bf16(s[2 * g + 1], aqh, kl[1], kl[3]);
                mma_bf16(s[2 * g + 1], aql, kh[1], kh[3]);
            }
        }

        const int dq = q0 - kb;
        if (dq < 128) {
            const int qr0 = wq * 16 + (lane >> 2);
            const int kbn = (lane & 3) << 1;
            const int th0 = qr0 + dq, th1 = qr0 + 8 + dq;
#pragma unroll
            for (int jb = 0; jb < 8; ++jb) {
                const int k0 = jb * 8 + kbn;
                if (k0 > th0)     s[jb][0] = -1e30f;
                if (k0 + 1 > th0) s[jb][1] = -1e30f;
                if (k0 > th1)     s[jb][2] = -1e30f;
                if (k0 + 1 > th1) s[jb][3] = -1e30f;
            }
        }

        float mx0 = -1e30f, mx1 = -1e30f;
#pragma unroll
        for (int jb = 0; jb < 8; ++jb) {
            mx0 = fmaxf(mx0, fmaxf(s[jb][0], s[jb][1]));
            mx1 = fmaxf(mx1, fmaxf(s[jb][2], s[jb][3]));
        }
        mx0 = fmaxf(mx0, __shfl_xor_sync(0xffffffffu, mx0, 1));
        mx0 = fmaxf(mx0, __shfl_xor_sync(0xffffffffu, mx0, 2));
        mx1 = fmaxf(mx1, __shfl_xor_sync(0xffffffffu, mx1, 1));
        mx1 = fmaxf(mx1, __shfl_xor_sync(0xffffffffu, mx1, 2));
        const float mn0 = fmaxf(m0, mx0), mn1 = fmaxf(m1, mx1);
        const float c0 = __expf(m0 - mn0), c1 = __expf(m1 - mn1);
        float sum0 = 0.f, sum1 = 0.f;
#pragma unroll
        for (int jb = 0; jb < 8; ++jb) {
            s[jb][0] = __expf(s[jb][0] - mn0);
            s[jb][1] = __expf(s[jb][1] - mn0);
            s[jb][2] = __expf(s[jb][2] - mn1);
            s[jb][3] = __expf(s[jb][3] - mn1);
            sum0 += s[jb][0] + s[jb][1];
            sum1 += s[jb][2] + s[jb][3];
        }
        sum0 += __shfl_xor_sync(0xffffffffu, sum0, 1);
        sum0 += __shfl_xor_sync(0xffffffffu, sum0, 2);
        sum1 += __shfl_xor_sync(0xffffffffu, sum1, 1);
        sum1 += __shfl_xor_sync(0xffffffffu, sum1, 2);
        l0 = l0 * c0 + sum0;
        l1 = l1 * c1 + sum1;
        m0 = mn0; m1 = mn1;
#pragma unroll
        for (int db = 0; db < 8; ++db) {
            o_[db][0] *= c0; o_[db][1] *= c0;
            o_[db][2] *= c1; o_[db][3] *= c1;
        }

#pragma unroll
        for (int t = 0; t < 4; ++t) {
            uint32_t pah[4], pal[4];
            {
                const float f0 = s[2 * t][0], f1 = s[2 * t][1];
                const float f2 = s[2 * t][2], f3 = s[2 * t][3];
                __nv_bfloat16 h0 = __float2bfloat16(f0), h1 = __float2bfloat16(f1);
                __nv_bfloat16 h2 = __float2bfloat16(f2), h3 = __float2bfloat16(f3);
                pah[0] = packh(h0, h1);
                pah[1] = packh(h2, h3);
                pal[0] = packbf(f0 - __bfloat162float(h0), f1 - __bfloat162float(h1));
                pal[1] = packbf(f2 - __bfloat162float(h2), f3 - __bfloat162float(h3));
            }
            {
                const float f0 = s[2 * t + 1][0], f1 = s[2 * t + 1][1];
                const float f2 = s[2 * t + 1][2], f3 = s[2 * t + 1][3];
                __nv_bfloat16 h0 = __float2bfloat16(f0), h1 = __float2bfloat16(f1);
                __nv_bfloat16 h2 = __float2bfloat16(f2), h3 = __float2bfloat16(f3);
                pah[2] = packh(h0, h1);
                pah[3] = packh(h2, h3);
                pal[2] = packbf(f0 - __bfloat162float(h0), f1 - __bfloat162float(h1));
                pal[3] = packbf(f2 - __bfloat162float(h2), f3 - __bfloat162float(h3));
            }
#pragma unroll
            for (int g = 0; g < 4; ++g) {
                uint32_t o = (uint32_t)(t * 16 + vrow) * 128 + g * 32 + vcol;
                uint32_t sw = o ^ ((o >> 3) & 0x70);
                uint32_t vh[4], vl[4];
                ldsm4t(vh, tb + BT_VH + sw);
                ldsm4t(vl, tb + BT_VL + sw);
                mma_bf16(o_[2 * g],     pah, vh[0], vh[1]);
                mma_bf16(o_[2 * g],     pal, vh[0], vh[1]);
                mma_bf16(o_[2 * g],     pah, vl[0], vl[1]);
                mma_bf16(o_[2 * g + 1], pah, vh[2], vh[3]);
                mma_bf16(o_[2 * g + 1], pal, vh[2], vh[3]);
                mma_bf16(o_[2 * g + 1], pah, vl[2], vl[3]);
            }
        }
        __syncthreads();
    }

    const float inv0 = 1.0f / l0, inv1 = 1.0f / l1;
    const int r0g = q0 + wq * 16 + (lane >> 2);
    const size_t ro0 = base + (size_t)r0g * DM;
    const size_t ro1 = ro0 + (size_t)8 * DM;
    const int cb = (lane & 3) << 1;
#pragma unroll
    for (int db = 0; db < 8; ++db) {
        const int col = db * 8 + cb;
        {
            const float f0 = o_[db][0] * inv0, f1 = o_[db][1] * inv0;
            __nv_bfloat16 h0 = __float2bfloat16(f0), h1 = __float2bfloat16(f1);
            *reinterpret_cast<uint32_t*>(Eh + ro0 + col) = packh(h0, h1);
            *reinterpret_cast<uint32_t*>(El + ro0 + col) =
                packbf(f0 - __bfloat162float(h0), f1 - __bfloat162float(h1));
        }
        {
            const float f2 = o_[db][2] * inv1, f3 = o_[db][3] * inv1;
            __nv_bfloat16 h2 = __float2bfloat16(f2), h3 = __float2bfloat16(f3);
            *reinterpret_cast<uint32_t*>(Eh + ro1 + col) = packh(h2, h3);
            *reinterpret_cast<uint32_t*>(El + ro1 + col) =
                packbf(f2 - __bfloat162float(h2), f3 - __bfloat162float(h3));
        }
    }
}

// ---------------------------------------------------------------------------
// Launch
// ---------------------------------------------------------------------------
extern "C" void kernel_launch(void* const* d_in, const int* in_sizes, int n_in,
                              void* d_out, int out_size)
{
    const float* X  = (const float*)d_in[0];
    const float* Wq = (const float*)d_in[1];
    const float* bq = (const float*)d_in[2];
    const float* Wk = (const float*)d_in[3];
    const float* bk = (const float*)d_in[4];
    const float* Wv = (const float*)d_in[5];
    const float* bv = (const float*)d_in[6];
    const float* Wo = (const float*)d_in[7];
    const float* bo = (const float*)d_in[8];
    float* out = (float*)d_out;

    float *cosT, *sinT;
    __nv_bfloat16 *Qh, *Ql, *Kh, *Kl, *Vh, *Vl, *Eh, *El, *Xh, *Xl, *WTh, *WTl;
    cudaGetSymbolAddress((void**)&cosT, g_cosT);
    cudaGetSymbolAddress((void**)&sinT, g_sinT);
    cudaGetSymbolAddress((void**)&Qh, g_Qh);
    cudaGetSymbolAddress((void**)&Ql, g_Ql);
    cudaGetSymbolAddress((void**)&Kh, g_Kh);
    cudaGetSymbolAddress((void**)&Kl, g_Kl);
    cudaGetSymbolAddress((void**)&Vh, g_Vh);
    cudaGetSymbolAddress((void**)&Vl, g_Vl);
    cudaGetSymbolAddress((void**)&Eh, g_Eh);
    cudaGetSymbolAddress((void**)&El, g_El);
    cudaGetSymbolAddress((void**)&Xh, g_Xh);
    cudaGetSymbolAddress((void**)&Xl, g_Xl);
    cudaGetSymbolAddress((void**)&WTh, g_WTh);
    cudaGetSymbolAddress((void**)&WTl, g_WTl);

    cudaFuncSetAttribute(gemm_qkv, cudaFuncAttributeMaxDynamicSharedMemorySize, GEMM_SMEM);
    cudaFuncSetAttribute(gemm_mma, cudaFuncAttributeMaxDynamicSharedMemorySize, GEMM_SMEM);
    cudaFuncSetAttribute(attn_mma, cudaFuncAttributeMaxDynamicSharedMemorySize, ATTN_SMEM);

    const size_t WSZ = (size_t)DM * DM;

    rope_table_kernel<<<(SEQ * HALFD + 255) / 256, 256>>>(cosT, sinT);

    wsplit4_kernel<<<dim3(DM / 32, DM / 32, 4), dim3(32, 8)>>>(
        Wq, Wk, Wv, Wo, WTh, WTl);

    const int NP = MTOT * DM / 2;
    split_kernel<<<(NP + 255) / 256, 256>>>(X, Xh, Xl, NP);

    gemm_qkv<<<dim3(18, MTOT / 128), GTHREADS, GEMM_SMEM>>>(
        Xh, Xl, WTh, WTl, bq, bk, bv, cosT, sinT, Qh, Ql, Kh, Kl, Vh, Vl);

    attn_mma<<<dim3(SEQ / 128, BATCH * NHEAD), 256, ATTN_SMEM>>>(Qh, Ql, Kh, Kl,
                                                                 Vh, Vl, Eh, El);

    gemm_mma<<<dim3(DM / 128, MTOT / 128), GTHREADS, GEMM_SMEM>>>(
        Eh, El, WTh + 3 * WSZ, WTl + 3 * WSZ, bo, out);
}